// round 4
// baseline (speedup 1.0000x reference)
#include <cuda_runtime.h>
#include <cuda_fp16.h>

#define NPTS  50000
#define NEDGE 800000
#define HID   64
#define INC   16
#define OUTC  16

// Scratch: G[n][o][j] in fp16 (j contiguous) and cb[n][o] in fp32
__device__ __half g_Gh[(size_t)NPTS * 1024];
__device__ float  g_cb[NPTS * OUTC];
__device__ int    g_is64;

__device__ __forceinline__ float gelu_exact(float v) {
    return 0.5f * v * (1.0f + erff(v * 0.70710678118654752440f));
}

// Fused: dtype detect (block 0 warp 0) + out zeroing + cb precompute.
// cb[n,o] = sum_i bo[i*16+o] * x[n*16+i]
__global__ __launch_bounds__(256) void fused_init(
    const float* __restrict__ x, const float* __restrict__ bo,
    const int* __restrict__ ei32, float* __restrict__ out)
{
    int t = blockIdx.x * blockDim.x + threadIdx.x;
    if (blockIdx.x == 0 && threadIdx.x < 32) {
        int lane = threadIdx.x;
        int nz = (ei32[2 * lane + 1] != 0) || (ei32[2 * (lane + 32) + 1] != 0);
        unsigned any = __ballot_sync(0xffffffffu, nz);
        if (lane == 0) g_is64 = (any == 0u);
    }
    if (t < NPTS * OUTC) {
        int n = t >> 4, o = t & 15;
        float acc = 0.0f;
        #pragma unroll
        for (int i = 0; i < 16; i++) acc += bo[i * 16 + o] * x[n * 16 + i];
        g_cb[t] = acc;
        out[t] = 0.0f;
    }
}

// G[n, o*64+j] = sum_i Wo[j*256 + i*16 + o] * x[n*16+i], stored fp16
__global__ __launch_bounds__(256) void precompute_G(
    const float* __restrict__ x, const float* __restrict__ Wo)
{
    __shared__ float sx[16 * 16];          // 16 nodes x 16 channels
    int base = blockIdx.x * 16;
    int tid = threadIdx.x;
    sx[tid] = x[base * 16 + tid];
    __syncthreads();

    for (int c = tid; c < 1024; c += 256) {
        int o = c >> 6, j = c & 63;
        float a[16];
        #pragma unroll
        for (int i = 0; i < 16; i++)
            a[i] = __ldg(&Wo[j * 256 + i * 16 + o]);   // 64KB, L1-resident after warmup
        #pragma unroll 4
        for (int n = 0; n < 16; n++) {
            const float* xp = sx + n * 16;
            float acc = 0.0f;
            #pragma unroll
            for (int i = 0; i < 16; i++) acc += a[i] * xp[i];
            g_Gh[(size_t)(base + n) * 1024 + c] = __float2half_rn(acc);
        }
    }
}

// One warp per edge (grid-strided). h1/h2 staged in per-warp smem; weights read
// as broadcast/row-major float4 LDS (no 128B scattered wavefronts, ~1 shfl/edge).
__global__ __launch_bounds__(256) void edge_kernel(
    const float* __restrict__ pos, const int* __restrict__ ei,
    const float* __restrict__ W1, const float* __restrict__ b1,
    const float* __restrict__ Wh, const float* __restrict__ bh,
    float* __restrict__ out)
{
    __shared__ float sW1[6 * 64];
    __shared__ float sb1[64];
    __shared__ float sbh[64];
    __shared__ float sWhT[64 * 68];       // transposed, padded: sWhT[c*68+j]
    __shared__ float sh1[8][64];          // per-warp h1
    __shared__ float sh2[8][64];          // per-warp h2

    int tid = threadIdx.x;
    for (int t = tid; t < 6 * 64; t += 256) sW1[t] = W1[t];
    if (tid < 64) { sb1[tid] = b1[tid]; sbh[tid] = bh[tid]; }
    for (int t = tid; t < 64 * 64; t += 256) {
        int j = t >> 6, c = t & 63;       // coalesced read of Wh[j*64+c]
        sWhT[c * 68 + j] = Wh[t];
    }
    __syncthreads();

    const int is64 = g_is64;   // uniform
    const unsigned F = 0xffffffffu;
    int lane = tid & 31;
    int w = tid >> 5;                             // warp in block
    int gw = (blockIdx.x * 256 + tid) >> 5;       // global warp id
    int nw = (gridDim.x * 256) >> 5;
    int c0 = lane, c1 = lane + 32;
    int o = lane & 15, half = lane >> 4;

    const float* whA = &sWhT[c0 * 68];
    const float* whB = &sWhT[c1 * 68];
    float* h1p = &sh1[w][0];
    float* h2p = &sh2[w][0];

    for (int e = gw; e < NEDGE; e += nw) {
        int src, dst;
        if (is64) { src = ei[2 * e]; dst = ei[2 * NEDGE + 2 * e]; }
        else      { src = ei[e];     dst = ei[NEDGE + e]; }

        float p0 = pos[src * 3 + 0], p1 = pos[src * 3 + 1], p2 = pos[src * 3 + 2];
        float p3 = pos[dst * 3 + 0], p4 = pos[dst * 3 + 1], p5 = pos[dst * 3 + 2];

        // ---- layer 1: channels (lane, lane+32) ----
        float a0 = sb1[c0];
        float a1 = sb1[c1];
        a0 += p0 * sW1[0 * 64 + c0]; a1 += p0 * sW1[0 * 64 + c1];
        a0 += p1 * sW1[1 * 64 + c0]; a1 += p1 * sW1[1 * 64 + c1];
        a0 += p2 * sW1[2 * 64 + c0]; a1 += p2 * sW1[2 * 64 + c1];
        a0 += p3 * sW1[3 * 64 + c0]; a1 += p3 * sW1[3 * 64 + c1];
        a0 += p4 * sW1[4 * 64 + c0]; a1 += p4 * sW1[4 * 64 + c1];
        a0 += p5 * sW1[5 * 64 + c0]; a1 += p5 * sW1[5 * 64 + c1];
        h1p[c0] = gelu_exact(a0);
        h1p[c1] = gelu_exact(a1);
        __syncwarp();

        // ---- layer 2: b = h1 @ WhT rows, broadcast h1 reads ----
        float b0 = sbh[c0];
        float b1v = sbh[c1];
        #pragma unroll
        for (int jb = 0; jb < 16; jb++) {
            float4 h  = *(const float4*)(h1p + jb * 4);   // broadcast
            float4 wA = *(const float4*)(whA + jb * 4);
            float4 wB = *(const float4*)(whB + jb * 4);
            b0  += h.x * wA.x + h.y * wA.y + h.z * wA.z + h.w * wA.w;
            b1v += h.x * wB.x + h.y * wB.y + h.z * wB.z + h.w * wB.w;
        }
        h2p[c0] = gelu_exact(b0);
        h2p[c1] = gelu_exact(b1v);
        __syncwarp();

        // ---- layer 3: m(o,half) = sum_{j in half's 32} h2[j] * G[src][o][j] ----
        const uint4* gp = (const uint4*)(g_Gh + (size_t)src * 1024 + (o * 64 + half * 32));
        const float* hp = h2p + half * 32;
        float m = 0.0f;
        #pragma unroll
        for (int k = 0; k < 4; k++) {
            uint4 gv = __ldg(gp + k);                 // 8 halves
            const __half2* h2v = (const __half2*)&gv;
            float4 ha = *(const float4*)(hp + k * 8);      // broadcast (16 lanes)
            float4 hb = *(const float4*)(hp + k * 8 + 4);
            float2 f0 = __half22float2(h2v[0]);
            float2 f1 = __half22float2(h2v[1]);
            float2 f2 = __half22float2(h2v[2]);
            float2 f3 = __half22float2(h2v[3]);
            m += f0.x * ha.x + f0.y * ha.y + f1.x * ha.z + f1.y * ha.w;
            m += f2.x * hb.x + f2.y * hb.y + f3.x * hb.z + f3.y * hb.w;
        }
        m += __shfl_down_sync(F, m, 16);              // combine j-halves

        if (lane < 16)
            atomicAdd(out + dst * 16 + o, m + __ldg(&g_cb[src * 16 + o]));
    }
}

extern "C" void kernel_launch(void* const* d_in, const int* in_sizes, int n_in,
                              void* d_out, int out_size) {
    const float* x   = (const float*)d_in[0];
    const float* pos = (const float*)d_in[1];
    const int*   ei  = (const int*)d_in[2];
    const float* W1  = (const float*)d_in[3];
    const float* b1  = (const float*)d_in[4];
    const float* Wh  = (const float*)d_in[5];
    const float* bh  = (const float*)d_in[6];
    const float* Wo  = (const float*)d_in[7];
    const float* bo  = (const float*)d_in[8];
    float* out = (float*)d_out;

    fused_init<<<(NPTS * OUTC + 255) / 256, 256>>>(x, bo, ei, out);
    precompute_G<<<NPTS / 16, 256>>>(x, Wo);
    edge_kernel<<<148 * 4, 256>>>(pos, ei, W1, b1, Wh, bh, out);
}

// round 7
// speedup vs baseline: 6.5767x; 6.5767x over previous
#include <cuda_runtime.h>
#include <cuda_fp16.h>

#define NPTS   50000
#define NEDGE  800000
#define NWTILE 25000      // 32 edges per warp-tile

__device__ float g_cb[NPTS * 16];
__device__ int   g_is64;

#define SWZ(b) ((b) ^ (((b) >> 3) & 0x70))

__device__ __forceinline__ unsigned smem_u32(const void* p) {
    unsigned a;
    asm("{ .reg .u64 t; cvta.to.shared.u64 t, %1; cvt.u32.u64 %0, t; }" : "=r"(a) : "l"(p));
    return a;
}

#define LDSM4(r0, r1, r2, r3, addr) \
    asm volatile("ldmatrix.sync.aligned.m8n8.x4.shared.b16 {%0,%1,%2,%3}, [%4];" \
        : "=r"(r0), "=r"(r1), "=r"(r2), "=r"(r3) : "r"(addr))

#define MMA16816(d, a0, a1, a2, a3, b0, b1) \
    asm volatile("mma.sync.aligned.m16n8k16.row.col.f32.f16.f16.f32 " \
        "{%0,%1,%2,%3}, {%4,%5,%6,%7}, {%8,%9}, {%0,%1,%2,%3};" \
        : "+f"((d)[0]), "+f"((d)[1]), "+f"((d)[2]), "+f"((d)[3]) \
        : "r"(a0), "r"(a1), "r"(a2), "r"(a3), "r"(b0), "r"(b1))

__device__ __forceinline__ float gelu_exact(float v) {
    return 0.5f * v * (1.0f + erff(v * 0.70710678118654752440f));
}
__device__ __forceinline__ unsigned h2u(float a, float b) {
    __half2 h = __floats2half2_rn(a, b);
    return *(unsigned*)&h;
}

// -------- fused init: dtype detect + zero out + cb[n,o] = sum_i bo[i*16+o]*x[n,i] ----
__global__ __launch_bounds__(256) void fused_init(
    const float* __restrict__ x, const float* __restrict__ bo,
    const int* __restrict__ ei32, float* __restrict__ out)
{
    int t = blockIdx.x * blockDim.x + threadIdx.x;
    if (blockIdx.x == 0 && threadIdx.x < 32) {
        int lane = threadIdx.x;
        int nz = (ei32[2 * lane + 1] != 0) || (ei32[2 * (lane + 32) + 1] != 0);
        unsigned any = __ballot_sync(0xffffffffu, nz);
        if (lane == 0) g_is64 = (any == 0u);
    }
    if (t < NPTS * 16) {
        int n = t >> 4, o = t & 15;
        float acc = 0.0f;
        #pragma unroll
        for (int i = 0; i < 16; i++) acc += bo[i * 16 + o] * x[n * 16 + i];
        g_cb[t] = acc;
        out[t] = 0.0f;
    }
}

// -------- edge kernel: warp-autonomous 32-edge tiles, mma.sync for layers 2-3 ----
__global__ __launch_bounds__(128) void edge_kernel(
    const float* __restrict__ x, const float* __restrict__ pos,
    const int* __restrict__ ei,
    const float* __restrict__ W1, const float* __restrict__ b1,
    const float* __restrict__ bh, const float* __restrict__ Wh,
    const float* __restrict__ Wo, float* __restrict__ out)
{
    extern __shared__ char dyn[];
    __shared__ float sW1[384], sb1[64];
    __shared__ float sx[128 * 17];
    __shared__ int   ssrc[128], sdst[128];

    unsigned dbase = smem_u32(dyn);
    unsigned abase = (dbase + 1023u) & ~1023u;
    char* sp = dyn + (abase - dbase);
    const unsigned H_OFF = 0, WH_OFF = 16384, WO_OFF = 24576;
    unsigned Hs = abase + H_OFF, WHs = abase + WH_OFF, WOs = abase + WO_OFF;

    int tid = threadIdx.x, lane = tid & 31, wid = tid >> 5;

    for (int t = tid; t < 384; t += 128) sW1[t] = W1[t];
    if (tid < 64) sb1[tid] = b1[tid];
    // WhT[c][j] = Wh[j*64+c]  (B^T rows: n-index row, k contiguous), fp16, SW128
    for (int t = tid; t < 4096; t += 128) {
        int j = t >> 6, c = t & 63;
        *(__half*)(sp + WH_OFF + SWZ(c * 128 + j * 2)) = __float2half_rn(Wh[t]);
    }
    // WoT[p][j] = Wo[j*256+p]
    for (int t = tid; t < 16384; t += 128) {
        int j = t >> 8, p = t & 255;
        *(__half*)(sp + WO_OFF + SWZ(p * 128 + j * 2)) = __float2half_rn(Wo[t]);
    }
    __syncthreads();

    const int is64 = g_is64;
    const int g = lane >> 2, tig = lane & 3;
    const int wb = wid * 32;

    float bhr[16];
    #pragma unroll
    for (int nt = 0; nt < 8; nt++) {
        bhr[2 * nt]     = __ldg(&bh[nt * 8 + 2 * tig]);
        bhr[2 * nt + 1] = __ldg(&bh[nt * 8 + 2 * tig + 1]);
    }

    const float4* W1q = (const float4*)sW1;
    const float4* b1q = (const float4*)sb1;

    int gw = blockIdx.x * 4 + wid;
    int nw = gridDim.x * 4;

    for (int t = gw; t < NWTILE; t += nw) {
        __syncwarp();
        int row = wb + lane;
        int e = t * 32 + lane;
        int src, dst;
        if (is64) { src = ei[2 * e]; dst = ei[2 * NEDGE + 2 * e]; }
        else      { src = ei[e];     dst = ei[NEDGE + e]; }
        ssrc[row] = src; sdst[row] = dst;

        {   // stage x[src] into padded smem row
            const float4* xp = (const float4*)(x + (size_t)src * 16);
            #pragma unroll
            for (int k = 0; k < 4; k++) {
                float4 v = __ldg(xp + k);
                sx[row * 17 + 4 * k]     = v.x; sx[row * 17 + 4 * k + 1] = v.y;
                sx[row * 17 + 4 * k + 2] = v.z; sx[row * 17 + 4 * k + 3] = v.w;
            }
        }
        float P[6];
        #pragma unroll
        for (int d = 0; d < 3; d++) {
            P[d]     = __ldg(&pos[src * 3 + d]);
            P[3 + d] = __ldg(&pos[dst * 3 + d]);
        }

        // ---- layer 1 (FFMA): 64 gelu outputs -> fp16 row in H ----
        unsigned rowb = (unsigned)row * 128;
        #pragma unroll
        for (int cc = 0; cc < 8; cc++) {
            float4 A = b1q[2 * cc], B = b1q[2 * cc + 1];
            #pragma unroll
            for (int d = 0; d < 6; d++) {
                float4 wA = W1q[d * 16 + 2 * cc];
                float4 wB = W1q[d * 16 + 2 * cc + 1];
                A.x += P[d] * wA.x; A.y += P[d] * wA.y; A.z += P[d] * wA.z; A.w += P[d] * wA.w;
                B.x += P[d] * wB.x; B.y += P[d] * wB.y; B.z += P[d] * wB.z; B.w += P[d] * wB.w;
            }
            uint4 u;
            u.x = h2u(gelu_exact(A.x), gelu_exact(A.y));
            u.y = h2u(gelu_exact(A.z), gelu_exact(A.w));
            u.z = h2u(gelu_exact(B.x), gelu_exact(B.y));
            u.w = h2u(gelu_exact(B.z), gelu_exact(B.w));
            *(uint4*)(sp + H_OFF + SWZ(rowb + cc * 16)) = u;
        }
        __syncwarp();

        // ---- A fragments of h1 ----
        unsigned a[2][4][4];
        #pragma unroll
        for (int mt = 0; mt < 2; mt++)
            #pragma unroll
            for (int kc = 0; kc < 4; kc++) {
                unsigned addr = Hs + SWZ((unsigned)(wb + mt * 16 + (lane & 15)) * 128
                                         + kc * 32 + (lane >> 4) * 16);
                LDSM4(a[mt][kc][0], a[mt][kc][1], a[mt][kc][2], a[mt][kc][3], addr);
            }

        // ---- MMA2: h2acc[32,64] = h1 @ Wh ----
        float acc[2][8][4];
        #pragma unroll
        for (int nt = 0; nt < 8; nt++) {
            unsigned b0, b1r, b2, b3, b4, b5, b6, b7;
            unsigned ba0 = WHs + SWZ((unsigned)(nt * 8 + (lane & 7)) * 128 + (lane >> 3) * 16);
            unsigned ba1 = WHs + SWZ((unsigned)(nt * 8 + (lane & 7)) * 128 + (4 + (lane >> 3)) * 16);
            LDSM4(b0, b1r, b2, b3, ba0);
            LDSM4(b4, b5, b6, b7, ba1);
            #pragma unroll
            for (int mt = 0; mt < 2; mt++) {
                float* d = acc[mt][nt];
                d[0] = d[1] = d[2] = d[3] = 0.0f;
                MMA16816(d, a[mt][0][0], a[mt][0][1], a[mt][0][2], a[mt][0][3], b0, b1r);
                MMA16816(d, a[mt][1][0], a[mt][1][1], a[mt][1][2], a[mt][1][3], b2, b3);
                MMA16816(d, a[mt][2][0], a[mt][2][1], a[mt][2][2], a[mt][2][3], b4, b5);
                MMA16816(d, a[mt][3][0], a[mt][3][1], a[mt][3][2], a[mt][3][3], b6, b7);
            }
        }

        // ---- gelu(h2+bh) -> fp16 back to H (same warp-owned rows) ----
        #pragma unroll
        for (int mt = 0; mt < 2; mt++)
            #pragma unroll
            for (int nt = 0; nt < 8; nt++) {
                int r1 = wb + mt * 16 + g;
                unsigned cby = (unsigned)(nt * 16 + tig * 4);
                *(__half2*)(sp + H_OFF + SWZ((unsigned)r1 * 128 + cby)) =
                    __floats2half2_rn(gelu_exact(acc[mt][nt][0] + bhr[2 * nt]),
                                      gelu_exact(acc[mt][nt][1] + bhr[2 * nt + 1]));
                *(__half2*)(sp + H_OFF + SWZ((unsigned)(r1 + 8) * 128 + cby)) =
                    __floats2half2_rn(gelu_exact(acc[mt][nt][2] + bhr[2 * nt]),
                                      gelu_exact(acc[mt][nt][3] + bhr[2 * nt + 1]));
            }
        __syncwarp();

        // ---- A fragments of h2 ----
        #pragma unroll
        for (int mt = 0; mt < 2; mt++)
            #pragma unroll
            for (int kc = 0; kc < 4; kc++) {
                unsigned addr = Hs + SWZ((unsigned)(wb + mt * 16 + (lane & 15)) * 128
                                         + kc * 32 + (lane >> 4) * 16);
                LDSM4(a[mt][kc][0], a[mt][kc][1], a[mt][kc][2], a[mt][kc][3], addr);
            }

        // ---- msg partials init with cb[src,o] ----
        float msg[16];
        #pragma unroll
        for (int mr = 0; mr < 4; mr++) {
            int row_ = wb + (mr >> 1) * 16 + g + (mr & 1) * 8;
            int s_ = ssrc[row_];
            #pragma unroll
            for (int q = 0; q < 4; q++) {
                int o = (q >> 1) * 8 + 2 * tig + (q & 1);
                msg[mr * 4 + q] = __ldg(&g_cb[s_ * 16 + o]);
            }
        }

        // ---- MMA3 in 4 chunks of 64 cols + fragment-local x contraction ----
        #pragma unroll
        for (int ch = 0; ch < 4; ch++) {
            #pragma unroll
            for (int nt = 0; nt < 8; nt++) {
                unsigned prow = (unsigned)(ch * 64 + nt * 8 + (lane & 7)) * 128;
                unsigned b0, b1r, b2, b3, b4, b5, b6, b7;
                LDSM4(b0, b1r, b2, b3, WOs + SWZ(prow + (lane >> 3) * 16));
                LDSM4(b4, b5, b6, b7, WOs + SWZ(prow + (4 + (lane >> 3)) * 16));
                #pragma unroll
                for (int mt = 0; mt < 2; mt++) {
                    float* d = acc[mt][nt];
                    d[0] = d[1] = d[2] = d[3] = 0.0f;
                    MMA16816(d, a[mt][0][0], a[mt][0][1], a[mt][0][2], a[mt][0][3], b0, b1r);
                    MMA16816(d, a[mt][1][0], a[mt][1][1], a[mt][1][2], a[mt][1][3], b2, b3);
                    MMA16816(d, a[mt][2][0], a[mt][2][1], a[mt][2][2], a[mt][2][3], b4, b5);
                    MMA16816(d, a[mt][3][0], a[mt][3][1], a[mt][3][2], a[mt][3][3], b6, b7);
                }
            }
            #pragma unroll
            for (int mt = 0; mt < 2; mt++)
                #pragma unroll
                for (int nt = 0; nt < 8; nt++) {
                    int i = 4 * ch + (nt >> 1);
                    int r1 = wb + mt * 16 + g;
                    float xv1 = sx[r1 * 17 + i];
                    float xv2 = sx[(r1 + 8) * 17 + i];
                    int op = (nt & 1) * 2;
                    msg[(mt * 2 + 0) * 4 + op]     += acc[mt][nt][0] * xv1;
                    msg[(mt * 2 + 0) * 4 + op + 1] += acc[mt][nt][1] * xv1;
                    msg[(mt * 2 + 1) * 4 + op]     += acc[mt][nt][2] * xv2;
                    msg[(mt * 2 + 1) * 4 + op + 1] += acc[mt][nt][3] * xv2;
                }
        }

        // ---- scatter: each (row,o) owned by exactly one lane ----
        #pragma unroll
        for (int mr = 0; mr < 4; mr++) {
            int row_ = wb + (mr >> 1) * 16 + g + (mr & 1) * 8;
            int d_ = sdst[row_];
            #pragma unroll
            for (int q = 0; q < 4; q++) {
                int o = (q >> 1) * 8 + 2 * tig + (q & 1);
                atomicAdd(out + (size_t)d_ * 16 + o, msg[mr * 4 + q]);
            }
        }
    }
}

extern "C" void kernel_launch(void* const* d_in, const int* in_sizes, int n_in,
                              void* d_out, int out_size) {
    const float* x   = (const float*)d_in[0];
    const float* pos = (const float*)d_in[1];
    const int*   ei  = (const int*)d_in[2];
    const float* W1  = (const float*)d_in[3];
    const float* b1  = (const float*)d_in[4];
    const float* Wh  = (const float*)d_in[5];
    const float* bh  = (const float*)d_in[6];
    const float* Wo  = (const float*)d_in[7];
    const float* bo  = (const float*)d_in[8];
    float* out = (float*)d_out;

    cudaFuncSetAttribute(edge_kernel, cudaFuncAttributeMaxDynamicSharedMemorySize, 58368);

    fused_init<<<(NPTS * 16 + 255) / 256, 256>>>(x, bo, ei, out);
    edge_kernel<<<444, 128, 58368>>>(x, pos, ei, W1, b1, bh, Wh, Wo, out);
}

// round 8
// speedup vs baseline: 8.4653x; 1.2872x over previous
#include <cuda_runtime.h>
#include <cuda_fp16.h>

#define NPTS   50000
#define NEDGE  800000
#define NWTILE 25000      // 32 edges per warp-tile

__device__ float g_cb[NPTS * 16];
__device__ int   g_is64;

#define SWZ(b) ((b) ^ (((b) >> 3) & 0x70))

__device__ __forceinline__ unsigned smem_u32(const void* p) {
    unsigned a;
    asm("{ .reg .u64 t; cvta.to.shared.u64 t, %1; cvt.u32.u64 %0, t; }" : "=r"(a) : "l"(p));
    return a;
}

#define LDSM4(r0, r1, r2, r3, addr) \
    asm volatile("ldmatrix.sync.aligned.m8n8.x4.shared.b16 {%0,%1,%2,%3}, [%4];" \
        : "=r"(r0), "=r"(r1), "=r"(r2), "=r"(r3) : "r"(addr))

#define MMA16816(d, a0, a1, a2, a3, b0, b1) \
    asm volatile("mma.sync.aligned.m16n8k16.row.col.f32.f16.f16.f32 " \
        "{%0,%1,%2,%3}, {%4,%5,%6,%7}, {%8,%9}, {%0,%1,%2,%3};" \
        : "+f"((d)[0]), "+f"((d)[1]), "+f"((d)[2]), "+f"((d)[3]) \
        : "r"(a0), "r"(a1), "r"(a2), "r"(a3), "r"(b0), "r"(b1))

__device__ __forceinline__ float gelu_exact(float v) {
    return 0.5f * v * (1.0f + erff(v * 0.70710678118654752440f));
}
__device__ __forceinline__ unsigned h2u(float a, float b) {
    __half2 h = __floats2half2_rn(a, b);
    return *(unsigned*)&h;
}

// -------- fused init: dtype detect + zero out + cb[n,o] = sum_i bo[i*16+o]*x[n,i] ----
__global__ __launch_bounds__(256) void fused_init(
    const float* __restrict__ x, const float* __restrict__ bo,
    const int* __restrict__ ei32, float* __restrict__ out)
{
    int t = blockIdx.x * blockDim.x + threadIdx.x;
    if (blockIdx.x == 0 && threadIdx.x < 32) {
        int lane = threadIdx.x;
        int nz = (ei32[2 * lane + 1] != 0) || (ei32[2 * (lane + 32) + 1] != 0);
        unsigned any = __ballot_sync(0xffffffffu, nz);
        if (lane == 0) g_is64 = (any == 0u);
    }
    if (t < NPTS * 16) {
        int n = t >> 4, o = t & 15;
        float acc = 0.0f;
        #pragma unroll
        for (int i = 0; i < 16; i++) acc += bo[i * 16 + o] * x[n * 16 + i];
        g_cb[t] = acc;
        out[t] = 0.0f;
    }
}

// -------- edge kernel: 8 warp-autonomous 32-edge tiles per CTA, mma.sync ----
__global__ __launch_bounds__(256, 2) void edge_kernel(
    const float* __restrict__ x, const float* __restrict__ pos,
    const int* __restrict__ ei,
    const float* __restrict__ W1, const float* __restrict__ b1,
    const float* __restrict__ bh, const float* __restrict__ Wh,
    const float* __restrict__ Wo, float* __restrict__ out)
{
    extern __shared__ char dyn[];
    __shared__ float sW1[384], sb1[64], sbh[64];
    __shared__ float sx[256 * 17];
    __shared__ int   ssrc[256], sdst[256];

    unsigned dbase = smem_u32(dyn);
    unsigned abase = (dbase + 1023u) & ~1023u;
    char* sp = dyn + (abase - dbase);
    const unsigned H_OFF = 0, WH_OFF = 32768, WO_OFF = 40960;
    unsigned Hs = abase + H_OFF, WHs = abase + WH_OFF, WOs = abase + WO_OFF;

    int tid = threadIdx.x, lane = tid & 31, wid = tid >> 5;

    for (int t = tid; t < 384; t += 256) sW1[t] = W1[t];
    if (tid < 64) { sb1[tid] = b1[tid]; sbh[tid] = bh[tid]; }
    // WhT[c][j] = Wh[j*64+c]  (B^T rows: n-index row, k contiguous), fp16, SW128
    for (int t = tid; t < 4096; t += 256) {
        int j = t >> 6, c = t & 63;
        *(__half*)(sp + WH_OFF + SWZ(c * 128 + j * 2)) = __float2half_rn(Wh[t]);
    }
    // WoT[p][j] = Wo[j*256+p]
    for (int t = tid; t < 16384; t += 256) {
        int j = t >> 8, p = t & 255;
        *(__half*)(sp + WO_OFF + SWZ(p * 128 + j * 2)) = __float2half_rn(Wo[t]);
    }
    __syncthreads();

    const int is64 = g_is64;
    const int g = lane >> 2, tig = lane & 3;
    const int wb = wid * 32;

    const float4* W1q = (const float4*)sW1;
    const float4* b1q = (const float4*)sb1;

    int gw = blockIdx.x * 8 + wid;
    int nw = gridDim.x * 8;

    for (int t = gw; t < NWTILE; t += nw) {
        __syncwarp();
        int row = wb + lane;
        int e = t * 32 + lane;
        int src, dst;
        if (is64) { src = ei[2 * e]; dst = ei[2 * NEDGE + 2 * e]; }
        else      { src = ei[e];     dst = ei[NEDGE + e]; }
        ssrc[row] = src; sdst[row] = dst;

        {   // stage x[src] into padded smem row
            const float4* xp = (const float4*)(x + (size_t)src * 16);
            #pragma unroll
            for (int k = 0; k < 4; k++) {
                float4 v = __ldg(xp + k);
                sx[row * 17 + 4 * k]     = v.x; sx[row * 17 + 4 * k + 1] = v.y;
                sx[row * 17 + 4 * k + 2] = v.z; sx[row * 17 + 4 * k + 3] = v.w;
            }
        }
        float P[6];
        #pragma unroll
        for (int d = 0; d < 3; d++) {
            P[d]     = __ldg(&pos[src * 3 + d]);
            P[3 + d] = __ldg(&pos[dst * 3 + d]);
        }

        // ---- layer 1 (FFMA): 64 gelu outputs -> fp16 row in H ----
        unsigned rowb = (unsigned)row * 128;
        #pragma unroll
        for (int cc = 0; cc < 8; cc++) {
            float4 A = b1q[2 * cc], B = b1q[2 * cc + 1];
            #pragma unroll
            for (int d = 0; d < 6; d++) {
                float4 wA = W1q[d * 16 + 2 * cc];
                float4 wB = W1q[d * 16 + 2 * cc + 1];
                A.x += P[d] * wA.x; A.y += P[d] * wA.y; A.z += P[d] * wA.z; A.w += P[d] * wA.w;
                B.x += P[d] * wB.x; B.y += P[d] * wB.y; B.z += P[d] * wB.z; B.w += P[d] * wB.w;
            }
            uint4 u;
            u.x = h2u(gelu_exact(A.x), gelu_exact(A.y));
            u.y = h2u(gelu_exact(A.z), gelu_exact(A.w));
            u.z = h2u(gelu_exact(B.x), gelu_exact(B.y));
            u.w = h2u(gelu_exact(B.z), gelu_exact(B.w));
            *(uint4*)(sp + H_OFF + SWZ(rowb + cc * 16)) = u;
        }
        __syncwarp();

        // ---- A fragments of h1 ----
        unsigned a[2][4][4];
        #pragma unroll
        for (int mt = 0; mt < 2; mt++)
            #pragma unroll
            for (int kc = 0; kc < 4; kc++) {
                unsigned addr = Hs + SWZ((unsigned)(wb + mt * 16 + (lane & 15)) * 128
                                         + kc * 32 + (lane >> 4) * 16);
                LDSM4(a[mt][kc][0], a[mt][kc][1], a[mt][kc][2], a[mt][kc][3], addr);
            }

        // ---- MMA2 + gelu + writeback, folded per nt (acc live = 4 regs) ----
        #pragma unroll
        for (int nt = 0; nt < 8; nt++) {
            unsigned b0, b1r, b2, b3, b4, b5, b6, b7;
            unsigned ba0 = WHs + SWZ((unsigned)(nt * 8 + (lane & 7)) * 128 + (lane >> 3) * 16);
            unsigned ba1 = WHs + SWZ((unsigned)(nt * 8 + (lane & 7)) * 128 + (4 + (lane >> 3)) * 16);
            LDSM4(b0, b1r, b2, b3, ba0);
            LDSM4(b4, b5, b6, b7, ba1);
            float bh0 = sbh[nt * 8 + 2 * tig], bh1 = sbh[nt * 8 + 2 * tig + 1];
            #pragma unroll
            for (int mt = 0; mt < 2; mt++) {
                float d[4] = {0.0f, 0.0f, 0.0f, 0.0f};
                MMA16816(d, a[mt][0][0], a[mt][0][1], a[mt][0][2], a[mt][0][3], b0, b1r);
                MMA16816(d, a[mt][1][0], a[mt][1][1], a[mt][1][2], a[mt][1][3], b2, b3);
                MMA16816(d, a[mt][2][0], a[mt][2][1], a[mt][2][2], a[mt][2][3], b4, b5);
                MMA16816(d, a[mt][3][0], a[mt][3][1], a[mt][3][2], a[mt][3][3], b6, b7);
                int r1 = wb + mt * 16 + g;
                unsigned cby = (unsigned)(nt * 16 + tig * 4);
                *(__half2*)(sp + H_OFF + SWZ((unsigned)r1 * 128 + cby)) =
                    __floats2half2_rn(gelu_exact(d[0] + bh0), gelu_exact(d[1] + bh1));
                *(__half2*)(sp + H_OFF + SWZ((unsigned)(r1 + 8) * 128 + cby)) =
                    __floats2half2_rn(gelu_exact(d[2] + bh0), gelu_exact(d[3] + bh1));
            }
        }
        __syncwarp();

        // ---- A fragments of h2 ----
        #pragma unroll
        for (int mt = 0; mt < 2; mt++)
            #pragma unroll
            for (int kc = 0; kc < 4; kc++) {
                unsigned addr = Hs + SWZ((unsigned)(wb + mt * 16 + (lane & 15)) * 128
                                         + kc * 32 + (lane >> 4) * 16);
                LDSM4(a[mt][kc][0], a[mt][kc][1], a[mt][kc][2], a[mt][kc][3], addr);
            }

        // ---- msg partials init with cb[src,o] ----
        float msg[16];
        #pragma unroll
        for (int mr = 0; mr < 4; mr++) {
            int row_ = wb + (mr >> 1) * 16 + g + (mr & 1) * 8;
            int s_ = ssrc[row_];
            #pragma unroll
            for (int q = 0; q < 4; q++) {
                int o = (q >> 1) * 8 + 2 * tig + (q & 1);
                msg[mr * 4 + q] = __ldg(&g_cb[s_ * 16 + o]);
            }
        }

        // ---- MMA3: fold x-contraction per (ch, nt, mt) (acc live = 4 regs) ----
        #pragma unroll
        for (int ch = 0; ch < 4; ch++) {
            #pragma unroll
            for (int nt = 0; nt < 8; nt++) {
                unsigned prow = (unsigned)(ch * 64 + nt * 8 + (lane & 7)) * 128;
                unsigned b0, b1r, b2, b3, b4, b5, b6, b7;
                LDSM4(b0, b1r, b2, b3, WOs + SWZ(prow + (lane >> 3) * 16));
                LDSM4(b4, b5, b6, b7, WOs + SWZ(prow + (4 + (lane >> 3)) * 16));
                int i = 4 * ch + (nt >> 1);
                int op = (nt & 1) * 2;
                #pragma unroll
                for (int mt = 0; mt < 2; mt++) {
                    float d[4] = {0.0f, 0.0f, 0.0f, 0.0f};
                    MMA16816(d, a[mt][0][0], a[mt][0][1], a[mt][0][2], a[mt][0][3], b0, b1r);
                    MMA16816(d, a[mt][1][0], a[mt][1][1], a[mt][1][2], a[mt][1][3], b2, b3);
                    MMA16816(d, a[mt][2][0], a[mt][2][1], a[mt][2][2], a[mt][2][3], b4, b5);
                    MMA16816(d, a[mt][3][0], a[mt][3][1], a[mt][3][2], a[mt][3][3], b6, b7);
                    int r1 = wb + mt * 16 + g;
                    float xv1 = sx[r1 * 17 + i];
                    float xv2 = sx[(r1 + 8) * 17 + i];
                    msg[(mt * 2 + 0) * 4 + op]     += d[0] * xv1;
                    msg[(mt * 2 + 0) * 4 + op + 1] += d[1] * xv1;
                    msg[(mt * 2 + 1) * 4 + op]     += d[2] * xv2;
                    msg[(mt * 2 + 1) * 4 + op + 1] += d[3] * xv2;
                }
            }
        }

        // ---- scatter: each (row,o) owned by exactly one lane ----
        #pragma unroll
        for (int mr = 0; mr < 4; mr++) {
            int row_ = wb + (mr >> 1) * 16 + g + (mr & 1) * 8;
            int d_ = sdst[row_];
            #pragma unroll
            for (int q = 0; q < 4; q++) {
                int o = (q >> 1) * 8 + 2 * tig + (q & 1);
                atomicAdd(out + (size_t)d_ * 16 + o, msg[mr * 4 + q]);
            }
        }
    }
}

extern "C" void kernel_launch(void* const* d_in, const int* in_sizes, int n_in,
                              void* d_out, int out_size) {
    const float* x   = (const float*)d_in[0];
    const float* pos = (const float*)d_in[1];
    const int*   ei  = (const int*)d_in[2];
    const float* W1  = (const float*)d_in[3];
    const float* b1  = (const float*)d_in[4];
    const float* Wh  = (const float*)d_in[5];
    const float* bh  = (const float*)d_in[6];
    const float* Wo  = (const float*)d_in[7];
    const float* bo  = (const float*)d_in[8];
    float* out = (float*)d_out;

    cudaFuncSetAttribute(edge_kernel, cudaFuncAttributeMaxDynamicSharedMemorySize, 73728);

    fused_init<<<(NPTS * 16 + 255) / 256, 256>>>(x, bo, ei, out);
    edge_kernel<<<296, 256, 73728>>>(x, pos, ei, W1, b1, bh, Wh, Wo, out);
}

// round 9
// speedup vs baseline: 9.2847x; 1.0968x over previous
#include <cuda_runtime.h>
#include <cuda_fp16.h>

#define NPTS   50000
#define NEDGE  800000
#define NWTILE 25000      // 32 edges per warp-tile

__device__ float g_cb[NPTS * 16];
__device__ int   g_is64;

#define SWZ(b) ((b) ^ (((b) >> 3) & 0x70))

__device__ __forceinline__ unsigned smem_u32(const void* p) {
    unsigned a;
    asm("{ .reg .u64 t; cvta.to.shared.u64 t, %1; cvt.u32.u64 %0, t; }" : "=r"(a) : "l"(p));
    return a;
}

#define LDSM4(r0, r1, r2, r3, addr) \
    asm volatile("ldmatrix.sync.aligned.m8n8.x4.shared.b16 {%0,%1,%2,%3}, [%4];" \
        : "=r"(r0), "=r"(r1), "=r"(r2), "=r"(r3) : "r"(addr))

#define MMA16816(d, a0, a1, a2, a3, b0, b1) \
    asm volatile("mma.sync.aligned.m16n8k16.row.col.f32.f16.f16.f32 " \
        "{%0,%1,%2,%3}, {%4,%5,%6,%7}, {%8,%9}, {%0,%1,%2,%3};" \
        : "+f"((d)[0]), "+f"((d)[1]), "+f"((d)[2]), "+f"((d)[3]) \
        : "r"(a0), "r"(a1), "r"(a2), "r"(a3), "r"(b0), "r"(b1))

#define MMA16808(d, a0, a1, b0) \
    asm volatile("mma.sync.aligned.m16n8k8.row.col.f32.f16.f16.f32 " \
        "{%0,%1,%2,%3}, {%4,%5}, {%6}, {%0,%1,%2,%3};" \
        : "+f"((d)[0]), "+f"((d)[1]), "+f"((d)[2]), "+f"((d)[3]) \
        : "r"(a0), "r"(a1), "r"(b0))

__device__ __forceinline__ float gelu_exact(float v) {
    return 0.5f * v * (1.0f + erff(v * 0.70710678118654752440f));
}
__device__ __forceinline__ unsigned h2u(float a, float b) {
    __half2 h = __floats2half2_rn(a, b);
    return *(unsigned*)&h;
}

// -------- fused init: dtype detect + zero out + cb[n,o] = sum_i bo[i*16+o]*x[n,i] ----
__global__ __launch_bounds__(256) void fused_init(
    const float* __restrict__ x, const float* __restrict__ bo,
    const int* __restrict__ ei32, float* __restrict__ out)
{
    int t = blockIdx.x * blockDim.x + threadIdx.x;
    if (blockIdx.x == 0 && threadIdx.x < 32) {
        int lane = threadIdx.x;
        int nz = (ei32[2 * lane + 1] != 0) || (ei32[2 * (lane + 32) + 1] != 0);
        unsigned any = __ballot_sync(0xffffffffu, nz);
        if (lane == 0) g_is64 = (any == 0u);
    }
    if (t < NPTS * 16) {
        int n = t >> 4, o = t & 15;
        float acc = 0.0f;
        #pragma unroll
        for (int i = 0; i < 16; i++) acc += bo[i * 16 + o] * x[n * 16 + i];
        g_cb[t] = acc;
        out[t] = 0.0f;
    }
}

// -------- edge kernel: frag-chained MMA pipeline, 8 warp-tiles per CTA ----
__global__ __launch_bounds__(256, 2) void edge_kernel(
    const float* __restrict__ x, const float* __restrict__ pos,
    const int* __restrict__ ei,
    const float* __restrict__ W1, const float* __restrict__ b1,
    const float* __restrict__ bh, const float* __restrict__ Wh,
    const float* __restrict__ Wo, float* __restrict__ out)
{
    extern __shared__ char dyn[];
    __shared__ float sbh[64];
    __shared__ float sx[256 * 17];
    __shared__ int   ssrc[256], sdst[256];
    __shared__ __align__(16) uint4 spe[256];

    unsigned dbase = smem_u32(dyn);
    unsigned abase = (dbase + 1023u) & ~1023u;
    char* sp = dyn + (abase - dbase);
    const unsigned WH_OFF = 0, WO_OFF = 8192;
    unsigned WHs = abase + WH_OFF, WOs = abase + WO_OFF;

    int tid = threadIdx.x, lane = tid & 31, wid = tid >> 5;

    if (tid < 64) sbh[tid] = bh[tid];
    // WhT[c][j] = Wh[j*64+c]  fp16 K-major rows of 128B, SW128
    for (int t = tid; t < 4096; t += 256) {
        int j = t >> 6, c = t & 63;
        *(__half*)(sp + WH_OFF + SWZ(c * 128 + j * 2)) = __float2half_rn(Wh[t]);
    }
    // WoT[p][j] = Wo[j*256+p]
    for (int t = tid; t < 16384; t += 256) {
        int j = t >> 8, p = t & 255;
        *(__half*)(sp + WO_OFF + SWZ(p * 128 + j * 2)) = __float2half_rn(Wo[t]);
    }
    __syncthreads();

    const int is64 = g_is64;
    const int g = lane >> 2, tig = lane & 3;
    const int wb = wid * 32;

    // W1 B-frags (k8n8), bias folded in as row 6 (pe[6]=1), row 7 = 0
    unsigned W1f[8];
    #pragma unroll
    for (int nt = 0; nt < 8; nt++) {
        int c = nt * 8 + g;
        W1f[nt] = (tig == 3) ? h2u(__ldg(&b1[c]), 0.0f)
                             : h2u(__ldg(&W1[(2 * tig) * 64 + c]),
                                   __ldg(&W1[(2 * tig + 1) * 64 + c]));
    }

    // hoisted swizzled B-address bases (prow multiples of 1024 add linearly)
    unsigned wh_a = WHs + SWZ((unsigned)(lane & 7) * 128 + (lane >> 3) * 16);
    unsigned wh_b = WHs + SWZ((unsigned)(lane & 7) * 128 + (4 + (lane >> 3)) * 16);
    unsigned wo_a = WOs + SWZ((unsigned)(lane & 7) * 128 + (lane >> 3) * 16);
    unsigned wo_b = WOs + SWZ((unsigned)(lane & 7) * 128 + (4 + (lane >> 3)) * 16);
    unsigned pe_addr = smem_u32(spe) + (unsigned)(wb + lane) * 16;

    int gw = blockIdx.x * 8 + wid;
    int nw = gridDim.x * 8;

    for (int t = gw; t < NWTILE; t += nw) {
        __syncwarp();
        int row = wb + lane;
        int e = t * 32 + lane;
        int src, dst;
        if (is64) { src = ei[2 * e]; dst = ei[2 * NEDGE + 2 * e]; }
        else      { src = ei[e];     dst = ei[NEDGE + e]; }
        ssrc[row] = src; sdst[row] = dst;

        {   // stage x[src] into padded smem row
            const float4* xp = (const float4*)(x + (size_t)src * 16);
            #pragma unroll
            for (int k = 0; k < 4; k++) {
                float4 v = __ldg(xp + k);
                sx[row * 17 + 4 * k]     = v.x; sx[row * 17 + 4 * k + 1] = v.y;
                sx[row * 17 + 4 * k + 2] = v.z; sx[row * 17 + 4 * k + 3] = v.w;
            }
        }
        {   // pe row: [pos_src, pos_dst, 1, 0] as 8 fp16 = one STS.128
            uint4 pev;
            pev.x = h2u(__ldg(&pos[src * 3 + 0]), __ldg(&pos[src * 3 + 1]));
            pev.y = h2u(__ldg(&pos[src * 3 + 2]), __ldg(&pos[dst * 3 + 0]));
            pev.z = h2u(__ldg(&pos[dst * 3 + 1]), __ldg(&pos[dst * 3 + 2]));
            pev.w = h2u(1.0f, 0.0f);
            spe[row] = pev;
        }
        __syncwarp();

        // ---- MMA1: h1 = gelu(pe @ [W1;b1;0]), outputs packed to A-frags ----
        unsigned pA0, pA1, pA2, pA3;
        LDSM4(pA0, pA1, pA2, pA3, pe_addr);

        unsigned h1f[2][4][4];
        #pragma unroll
        for (int kc = 0; kc < 4; kc++)
            #pragma unroll
            for (int par = 0; par < 2; par++) {
                unsigned b = W1f[2 * kc + par];
                #pragma unroll
                for (int mt = 0; mt < 2; mt++) {
                    float d[4] = {0.0f, 0.0f, 0.0f, 0.0f};
                    MMA16808(d, mt ? pA2 : pA0, mt ? pA3 : pA1, b);
                    h1f[mt][kc][2 * par]     = h2u(gelu_exact(d[0]), gelu_exact(d[1]));
                    h1f[mt][kc][2 * par + 1] = h2u(gelu_exact(d[2]), gelu_exact(d[3]));
                }
            }

        // ---- MMA2: h2 = gelu(h1 @ Wh + bh), frag-chained ----
        unsigned h2f[2][4][4];
        #pragma unroll
        for (int kc = 0; kc < 4; kc++)
            #pragma unroll
            for (int par = 0; par < 2; par++) {
                int nt = 2 * kc + par;
                unsigned b0, b1r, b2, b3, b4, b5, b6, b7;
                LDSM4(b0, b1r, b2, b3, wh_a + (unsigned)nt * 1024);
                LDSM4(b4, b5, b6, b7, wh_b + (unsigned)nt * 1024);
                float2 bh2 = *(const float2*)&sbh[nt * 8 + 2 * tig];
                #pragma unroll
                for (int mt = 0; mt < 2; mt++) {
                    float d[4] = {bh2.x, bh2.y, bh2.x, bh2.y};
                    MMA16816(d, h1f[mt][0][0], h1f[mt][0][1], h1f[mt][0][2], h1f[mt][0][3], b0, b1r);
                    MMA16816(d, h1f[mt][1][0], h1f[mt][1][1], h1f[mt][1][2], h1f[mt][1][3], b2, b3);
                    MMA16816(d, h1f[mt][2][0], h1f[mt][2][1], h1f[mt][2][2], h1f[mt][2][3], b4, b5);
                    MMA16816(d, h1f[mt][3][0], h1f[mt][3][1], h1f[mt][3][2], h1f[mt][3][3], b6, b7);
                    h2f[mt][kc][2 * par]     = h2u(gelu_exact(d[0]), gelu_exact(d[1]));
                    h2f[mt][kc][2 * par + 1] = h2u(gelu_exact(d[2]), gelu_exact(d[3]));
                }
            }

        // ---- msg partials init with cb[src,o] ----
        float msg[16];
        #pragma unroll
        for (int mr = 0; mr < 4; mr++) {
            int row_ = wb + (mr >> 1) * 16 + g + (mr & 1) * 8;
            int s_ = ssrc[row_];
            #pragma unroll
            for (int q = 0; q < 4; q++) {
                int o = (q >> 1) * 8 + 2 * tig + (q & 1);
                msg[mr * 4 + q] = __ldg(&g_cb[s_ * 16 + o]);
            }
        }

        // ---- MMA3: z = h2 @ Wo, fold x-contraction per (ch, nt, mt) ----
        #pragma unroll
        for (int ch = 0; ch < 4; ch++) {
            #pragma unroll
            for (int nt = 0; nt < 8; nt++) {
                unsigned prow = (unsigned)(ch * 64 + nt * 8) * 128;
                unsigned b0, b1r, b2, b3, b4, b5, b6, b7;
                LDSM4(b0, b1r, b2, b3, wo_a + prow);
                LDSM4(b4, b5, b6, b7, wo_b + prow);
                int i = 4 * ch + (nt >> 1);
                int op = (nt & 1) * 2;
                #pragma unroll
                for (int mt = 0; mt < 2; mt++) {
                    float d[4] = {0.0f, 0.0f, 0.0f, 0.0f};
                    MMA16816(d, h2f[mt][0][0], h2f[mt][0][1], h2f[mt][0][2], h2f[mt][0][3], b0, b1r);
                    MMA16816(d, h2f[mt][1][0], h2f[mt][1][1], h2f[mt][1][2], h2f[mt][1][3], b2, b3);
                    MMA16816(d, h2f[mt][2][0], h2f[mt][2][1], h2f[mt][2][2], h2f[mt][2][3], b4, b5);
                    MMA16816(d, h2f[mt][3][0], h2f[mt][3][1], h2f[mt][3][2], h2f[mt][3][3], b6, b7);
                    int r1 = wb + mt * 16 + g;
                    float xv1 = sx[r1 * 17 + i];
                    float xv2 = sx[(r1 + 8) * 17 + i];
                    msg[(mt * 2 + 0) * 4 + op]     += d[0] * xv1;
                    msg[(mt * 2 + 0) * 4 + op + 1] += d[1] * xv1;
                    msg[(mt * 2 + 1) * 4 + op]     += d[2] * xv2;
                    msg[(mt * 2 + 1) * 4 + op + 1] += d[3] * xv2;
                }
            }
        }

        // ---- scatter: each (row,o) owned by exactly one lane ----
        #pragma unroll
        for (int mr = 0; mr < 4; mr++) {
            int row_ = wb + (mr >> 1) * 16 + g + (mr & 1) * 8;
            int d_ = sdst[row_];
            #pragma unroll
            for (int q = 0; q < 4; q++) {
                int o = (q >> 1) * 8 + 2 * tig + (q & 1);
                atomicAdd(out + (size_t)d_ * 16 + o, msg[mr * 4 + q]);
            }
        }
    }
}

extern "C" void kernel_launch(void* const* d_in, const int* in_sizes, int n_in,
                              void* d_out, int out_size) {
    const float* x   = (const float*)d_in[0];
    const float* pos = (const float*)d_in[1];
    const int*   ei  = (const int*)d_in[2];
    const float* W1  = (const float*)d_in[3];
    const float* b1  = (const float*)d_in[4];
    const float* Wh  = (const float*)d_in[5];
    const float* bh  = (const float*)d_in[6];
    const float* Wo  = (const float*)d_in[7];
    const float* bo  = (const float*)d_in[8];
    float* out = (float*)d_out;

    cudaFuncSetAttribute(edge_kernel, cudaFuncAttributeMaxDynamicSharedMemorySize, 41984);

    fused_init<<<(NPTS * 16 + 255) / 256, 256>>>(x, bo, ei, out);
    edge_kernel<<<296, 256, 41984>>>(x, pos, ei, W1, b1, bh, Wh, Wo, out);
}

// round 10
// speedup vs baseline: 10.0384x; 1.0812x over previous
#include <cuda_runtime.h>
#include <cuda_fp16.h>

#define NPTS   50000
#define NEDGE  800000
#define NWTILE 25000      // 32 edges per warp-tile

__device__ float g_cb[NPTS * 16];
__device__ int   g_is64;

#define SWZ(b) ((b) ^ (((b) >> 3) & 0x70))

__device__ __forceinline__ unsigned smem_u32(const void* p) {
    unsigned a;
    asm("{ .reg .u64 t; cvta.to.shared.u64 t, %1; cvt.u32.u64 %0, t; }" : "=r"(a) : "l"(p));
    return a;
}

#define LDSM4(r0, r1, r2, r3, addr) \
    asm volatile("ldmatrix.sync.aligned.m8n8.x4.shared.b16 {%0,%1,%2,%3}, [%4];" \
        : "=r"(r0), "=r"(r1), "=r"(r2), "=r"(r3) : "r"(addr))

#define MMA16816(d, a0, a1, a2, a3, b0, b1) \
    asm volatile("mma.sync.aligned.m16n8k16.row.col.f32.f16.f16.f32 " \
        "{%0,%1,%2,%3}, {%4,%5,%6,%7}, {%8,%9}, {%0,%1,%2,%3};" \
        : "+f"((d)[0]), "+f"((d)[1]), "+f"((d)[2]), "+f"((d)[3]) \
        : "r"(a0), "r"(a1), "r"(a2), "r"(a3), "r"(b0), "r"(b1))

#define MMA16808(d, a0, a1, b0) \
    asm volatile("mma.sync.aligned.m16n8k8.row.col.f32.f16.f16.f32 " \
        "{%0,%1,%2,%3}, {%4,%5}, {%6}, {%0,%1,%2,%3};" \
        : "+f"((d)[0]), "+f"((d)[1]), "+f"((d)[2]), "+f"((d)[3]) \
        : "r"(a0), "r"(a1), "r"(b0))

// Branchless gelu: erf via Abramowitz-Stegun 7.1.26 (|eps| <= 1.5e-7),
// sign via copysign. ~14 instr, 2 MUFU, no branches. Error far below the
// fp16 quantization applied immediately after.
__device__ __forceinline__ float gelu_fast(float x) {
    float t = fabsf(x) * 0.70710678118654752440f;
    float k = __fdividef(1.0f, fmaf(0.3275911f, t, 1.0f));
    float p = fmaf(1.061405429f, k, -1.453152027f);
    p = fmaf(p, k, 1.421413741f);
    p = fmaf(p, k, -0.284496736f);
    p = fmaf(p, k, 0.254829592f);
    p *= k;
    float e = __expf(-t * t);
    float erf = fmaf(-p, e, 1.0f);                 // erf(t), t >= 0
    float phi = fmaf(copysignf(erf, x), 0.5f, 0.5f);
    return x * phi;
}
__device__ __forceinline__ float gelu_exact(float v) {
    return 0.5f * v * (1.0f + erff(v * 0.70710678118654752440f));
}
__device__ __forceinline__ unsigned h2u(float a, float b) {
    __half2 h = __floats2half2_rn(a, b);
    return *(unsigned*)&h;
}
__device__ __forceinline__ unsigned gelu2_pack(float a, float b) {
    return h2u(gelu_fast(a), gelu_fast(b));
}

// -------- fused init: dtype detect + zero out + cb[n,o] = sum_i bo[i*16+o]*x[n,i] ----
__global__ __launch_bounds__(256) void fused_init(
    const float* __restrict__ x, const float* __restrict__ bo,
    const int* __restrict__ ei32, float* __restrict__ out)
{
    int t = blockIdx.x * blockDim.x + threadIdx.x;
    if (blockIdx.x == 0 && threadIdx.x < 32) {
        int lane = threadIdx.x;
        int nz = (ei32[2 * lane + 1] != 0) || (ei32[2 * (lane + 32) + 1] != 0);
        unsigned any = __ballot_sync(0xffffffffu, nz);
        if (lane == 0) g_is64 = (any == 0u);
    }
    if (t < NPTS * 16) {
        int n = t >> 4, o = t & 15;
        float acc = 0.0f;
        #pragma unroll
        for (int i = 0; i < 16; i++) acc += bo[i * 16 + o] * x[n * 16 + i];
        g_cb[t] = acc;
        out[t] = 0.0f;
    }
}

// -------- edge kernel: frag-chained MMA pipeline, 8 warp-tiles per CTA ----
__global__ __launch_bounds__(256, 2) void edge_kernel(
    const float* __restrict__ x, const float* __restrict__ pos,
    const int* __restrict__ ei,
    const float* __restrict__ W1, const float* __restrict__ b1,
    const float* __restrict__ bh, const float* __restrict__ Wh,
    const float* __restrict__ Wo, float* __restrict__ out)
{
    extern __shared__ char dyn[];
    __shared__ float sbh[64];
    __shared__ float sx[256 * 17];
    __shared__ int   ssrc[256], sdst[256];
    __shared__ __align__(16) uint4 spe[256];

    unsigned dbase = smem_u32(dyn);
    unsigned abase = (dbase + 1023u) & ~1023u;
    char* sp = dyn + (abase - dbase);
    const unsigned WH_OFF = 0, WO_OFF = 8192;
    unsigned WHs = abase + WH_OFF, WOs = abase + WO_OFF;

    int tid = threadIdx.x, lane = tid & 31, wid = tid >> 5;

    if (tid < 64) sbh[tid] = bh[tid];
    // WhT[c][j] = Wh[j*64+c]  fp16 K-major rows of 128B, SW128
    for (int t = tid; t < 4096; t += 256) {
        int j = t >> 6, c = t & 63;
        *(__half*)(sp + WH_OFF + SWZ(c * 128 + j * 2)) = __float2half_rn(Wh[t]);
    }
    // WoT[p][j] = Wo[j*256+p]
    for (int t = tid; t < 16384; t += 256) {
        int j = t >> 8, p = t & 255;
        *(__half*)(sp + WO_OFF + SWZ(p * 128 + j * 2)) = __float2half_rn(Wo[t]);
    }
    __syncthreads();

    const int is64 = g_is64;
    const int g = lane >> 2, tig = lane & 3;
    const int wb = wid * 32;

    // W1 B-frags (k8n8), bias folded in as row 6 (pe[6]=1), row 7 = 0
    unsigned W1f[8];
    #pragma unroll
    for (int nt = 0; nt < 8; nt++) {
        int c = nt * 8 + g;
        W1f[nt] = (tig == 3) ? h2u(__ldg(&b1[c]), 0.0f)
                             : h2u(__ldg(&W1[(2 * tig) * 64 + c]),
                                   __ldg(&W1[(2 * tig + 1) * 64 + c]));
    }

    // hoisted swizzled B-address bases (row offsets that are 1024-multiples add linearly)
    unsigned wh_a = WHs + SWZ((unsigned)(lane & 7) * 128 + (lane >> 3) * 16);
    unsigned wh_b = WHs + SWZ((unsigned)(lane & 7) * 128 + (4 + (lane >> 3)) * 16);
    unsigned wo_a = WOs + SWZ((unsigned)(lane & 7) * 128 + (lane >> 3) * 16);
    unsigned wo_b = WOs + SWZ((unsigned)(lane & 7) * 128 + (4 + (lane >> 3)) * 16);
    unsigned pe_addr = smem_u32(spe) + (unsigned)(wb + lane) * 16;

    int gw = blockIdx.x * 8 + wid;
    int nw = gridDim.x * 8;

    for (int t = gw; t < NWTILE; t += nw) {
        __syncwarp();
        int row = wb + lane;
        int e = t * 32 + lane;
        int src, dst;
        if (is64) { src = ei[2 * e]; dst = ei[2 * NEDGE + 2 * e]; }
        else      { src = ei[e];     dst = ei[NEDGE + e]; }
        ssrc[row] = src; sdst[row] = dst;

        {   // stage x[src] into padded smem row
            const float4* xp = (const float4*)(x + (size_t)src * 16);
            #pragma unroll
            for (int k = 0; k < 4; k++) {
                float4 v = __ldg(xp + k);
                sx[row * 17 + 4 * k]     = v.x; sx[row * 17 + 4 * k + 1] = v.y;
                sx[row * 17 + 4 * k + 2] = v.z; sx[row * 17 + 4 * k + 3] = v.w;
            }
        }
        {   // pe row: [pos_src, pos_dst, 1, 0] as 8 fp16 = one STS.128
            uint4 pev;
            pev.x = h2u(__ldg(&pos[src * 3 + 0]), __ldg(&pos[src * 3 + 1]));
            pev.y = h2u(__ldg(&pos[src * 3 + 2]), __ldg(&pos[dst * 3 + 0]));
            pev.z = h2u(__ldg(&pos[dst * 3 + 1]), __ldg(&pos[dst * 3 + 2]));
            pev.w = h2u(1.0f, 0.0f);
            spe[row] = pev;
        }
        __syncwarp();

        // ---- MMA1: h1 = gelu(pe @ [W1;b1;0]), outputs packed to A-frags ----
        unsigned pA0, pA1, pA2, pA3;
        LDSM4(pA0, pA1, pA2, pA3, pe_addr);

        unsigned h1f[2][4][4];
        #pragma unroll
        for (int kc = 0; kc < 4; kc++)
            #pragma unroll
            for (int par = 0; par < 2; par++) {
                unsigned b = W1f[2 * kc + par];
                #pragma unroll
                for (int mt = 0; mt < 2; mt++) {
                    float d[4] = {0.0f, 0.0f, 0.0f, 0.0f};
                    MMA16808(d, mt ? pA2 : pA0, mt ? pA3 : pA1, b);
                    h1f[mt][kc][2 * par]     = gelu2_pack(d[0], d[1]);
                    h1f[mt][kc][2 * par + 1] = gelu2_pack(d[2], d[3]);
                }
            }

        // ---- MMA2: h2 = gelu(h1 @ Wh + bh), frag-chained ----
        unsigned h2f[2][4][4];
        #pragma unroll
        for (int kc = 0; kc < 4; kc++)
            #pragma unroll
            for (int par = 0; par < 2; par++) {
                int nt = 2 * kc + par;
                unsigned b0, b1r, b2, b3, b4, b5, b6, b7;
                LDSM4(b0, b1r, b2, b3, wh_a + (unsigned)nt * 1024);
                LDSM4(b4, b5, b6, b7, wh_b + (unsigned)nt * 1024);
                float2 bh2 = *(const float2*)&sbh[nt * 8 + 2 * tig];
                #pragma unroll
                for (int mt = 0; mt < 2; mt++) {
                    float d[4] = {bh2.x, bh2.y, bh2.x, bh2.y};
                    MMA16816(d, h1f[mt][0][0], h1f[mt][0][1], h1f[mt][0][2], h1f[mt][0][3], b0, b1r);
                    MMA16816(d, h1f[mt][1][0], h1f[mt][1][1], h1f[mt][1][2], h1f[mt][1][3], b2, b3);
                    MMA16816(d, h1f[mt][2][0], h1f[mt][2][1], h1f[mt][2][2], h1f[mt][2][3], b4, b5);
                    MMA16816(d, h1f[mt][3][0], h1f[mt][3][1], h1f[mt][3][2], h1f[mt][3][3], b6, b7);
                    h2f[mt][kc][2 * par]     = gelu2_pack(d[0], d[1]);
                    h2f[mt][kc][2 * par + 1] = gelu2_pack(d[2], d[3]);
                }
            }

        // ---- msg partials init with cb[src,o] ----
        float msg[16];
        #pragma unroll
        for (int mr = 0; mr < 4; mr++) {
            int row_ = wb + (mr >> 1) * 16 + g + (mr & 1) * 8;
            int s_ = ssrc[row_];
            #pragma unroll
            for (int q = 0; q < 4; q++) {
                int o = (q >> 1) * 8 + 2 * tig + (q & 1);
                msg[mr * 4 + q] = __ldg(&g_cb[s_ * 16 + o]);
            }
        }

        // ---- MMA3: z = h2 @ Wo; nt-pairs share i -> hoisted x loads ----
        #pragma unroll
        for (int ch = 0; ch < 4; ch++) {
            #pragma unroll
            for (int ntp = 0; ntp < 4; ntp++) {
                unsigned prow0 = (unsigned)(ch * 64 + (2 * ntp) * 8) * 128;
                unsigned prow1 = prow0 + 1024;
                unsigned b0, b1r, b2, b3, b4, b5, b6, b7;
                unsigned c0, c1r, c2, c3, c4, c5, c6, c7;
                LDSM4(b0, b1r, b2, b3, wo_a + prow0);
                LDSM4(b4, b5, b6, b7, wo_b + prow0);
                LDSM4(c0, c1r, c2, c3, wo_a + prow1);
                LDSM4(c4, c5, c6, c7, wo_b + prow1);
                int i = 4 * ch + ntp;
                #pragma unroll
                for (int mt = 0; mt < 2; mt++) {
                    int r1 = wb + mt * 16 + g;
                    float xv1 = sx[r1 * 17 + i];
                    float xv2 = sx[(r1 + 8) * 17 + i];
                    float d0[4] = {0.0f, 0.0f, 0.0f, 0.0f};
                    float d1[4] = {0.0f, 0.0f, 0.0f, 0.0f};
                    MMA16816(d0, h2f[mt][0][0], h2f[mt][0][1], h2f[mt][0][2], h2f[mt][0][3], b0, b1r);
                    MMA16816(d1, h2f[mt][0][0], h2f[mt][0][1], h2f[mt][0][2], h2f[mt][0][3], c0, c1r);
                    MMA16816(d0, h2f[mt][1][0], h2f[mt][1][1], h2f[mt][1][2], h2f[mt][1][3], b2, b3);
                    MMA16816(d1, h2f[mt][1][0], h2f[mt][1][1], h2f[mt][1][2], h2f[mt][1][3], c2, c3);
                    MMA16816(d0, h2f[mt][2][0], h2f[mt][2][1], h2f[mt][2][2], h2f[mt][2][3], b4, b5);
                    MMA16816(d1, h2f[mt][2][0], h2f[mt][2][1], h2f[mt][2][2], h2f[mt][2][3], c4, c5);
                    MMA16816(d0, h2f[mt][3][0], h2f[mt][3][1], h2f[mt][3][2], h2f[mt][3][3], b6, b7);
                    MMA16816(d1, h2f[mt][3][0], h2f[mt][3][1], h2f[mt][3][2], h2f[mt][3][3], c6, c7);
                    msg[(mt * 2 + 0) * 4 + 0] += d0[0] * xv1;
                    msg[(mt * 2 + 0) * 4 + 1] += d0[1] * xv1;
                    msg[(mt * 2 + 1) * 4 + 0] += d0[2] * xv2;
                    msg[(mt * 2 + 1) * 4 + 1] += d0[3] * xv2;
                    msg[(mt * 2 + 0) * 4 + 2] += d1[0] * xv1;
                    msg[(mt * 2 + 0) * 4 + 3] += d1[1] * xv1;
                    msg[(mt * 2 + 1) * 4 + 2] += d1[2] * xv2;
                    msg[(mt * 2 + 1) * 4 + 3] += d1[3] * xv2;
                }
            }
        }

        // ---- scatter: each (row,o) owned by exactly one lane ----
        #pragma unroll
        for (int mr = 0; mr < 4; mr++) {
            int row_ = wb + (mr >> 1) * 16 + g + (mr & 1) * 8;
            int d_ = sdst[row_];
            #pragma unroll
            for (int q = 0; q < 4; q++) {
                int o = (q >> 1) * 8 + 2 * tig + (q & 1);
                atomicAdd(out + (size_t)d_ * 16 + o, msg[mr * 4 + q]);
            }
        }
    }
}

extern "C" void kernel_launch(void* const* d_in, const int* in_sizes, int n_in,
                              void* d_out, int out_size) {
    const float* x   = (const float*)d_in[0];
    const float* pos = (const float*)d_in[1];
    const int*   ei  = (const int*)d_in[2];
    const float* W1  = (const float*)d_in[3];
    const float* b1  = (const float*)d_in[4];
    const float* Wh  = (const float*)d_in[5];
    const float* bh  = (const float*)d_in[6];
    const float* Wo  = (const float*)d_in[7];
    const float* bo  = (const float*)d_in[8];
    float* out = (float*)d_out;

    cudaFuncSetAttribute(edge_kernel, cudaFuncAttributeMaxDynamicSharedMemorySize, 41984);

    fused_init<<<(NPTS * 16 + 255) / 256, 256>>>(x, bo, ei, out);
    edge_kernel<<<296, 256, 41984>>>(x, pos, ei, W1, b1, bh, Wh, Wo, out);
}

// round 11
// speedup vs baseline: 11.1660x; 1.1123x over previous
#include <cuda_runtime.h>
#include <cuda_fp16.h>

#define NPTS   50000
#define NEDGE  800000
#define NWTILE 25000      // 32 edges per warp-tile

__device__ int g_is64;

#define SWZ(b) ((b) ^ (((b) >> 3) & 0x70))

__device__ __forceinline__ unsigned smem_u32(const void* p) {
    unsigned a;
    asm("{ .reg .u64 t; cvta.to.shared.u64 t, %1; cvt.u32.u64 %0, t; }" : "=r"(a) : "l"(p));
    return a;
}

#define LDSM4(r0, r1, r2, r3, addr) \
    asm volatile("ldmatrix.sync.aligned.m8n8.x4.shared.b16 {%0,%1,%2,%3}, [%4];" \
        : "=r"(r0), "=r"(r1), "=r"(r2), "=r"(r3) : "r"(addr))

#define MMA16816(d, a0, a1, a2, a3, b0, b1) \
    asm volatile("mma.sync.aligned.m16n8k16.row.col.f32.f16.f16.f32 " \
        "{%0,%1,%2,%3}, {%4,%5,%6,%7}, {%8,%9}, {%0,%1,%2,%3};" \
        : "+f"((d)[0]), "+f"((d)[1]), "+f"((d)[2]), "+f"((d)[3]) \
        : "r"(a0), "r"(a1), "r"(a2), "r"(a3), "r"(b0), "r"(b1))

#define MMA16808(d, a0, a1, b0) \
    asm volatile("mma.sync.aligned.m16n8k8.row.col.f32.f16.f16.f32 " \
        "{%0,%1,%2,%3}, {%4,%5}, {%6}, {%0,%1,%2,%3};" \
        : "+f"((d)[0]), "+f"((d)[1]), "+f"((d)[2]), "+f"((d)[3]) \
        : "r"(a0), "r"(a1), "r"(b0))

// Branchless gelu, erf via A-S 7.1.25 (3-term, |eps|<=2.5e-5, far below fp16 rounding).
__device__ __forceinline__ float gelu_fast(float x) {
    float t = fabsf(x) * 0.70710678118654752440f;
    float k = __fdividef(1.0f, fmaf(0.47047f, t, 1.0f));
    float p = fmaf(fmaf(0.7478556f, k, -0.0958798f), k, 0.3480242f) * k;
    float e = __expf(-t * t);
    float erf = fmaf(-p, e, 1.0f);
    float phi = fmaf(copysignf(erf, x), 0.5f, 0.5f);
    return x * phi;
}
__device__ __forceinline__ unsigned h2u(float a, float b) {
    __half2 h = __floats2half2_rn(a, b);
    return *(unsigned*)&h;
}
__device__ __forceinline__ unsigned gelu2_pack(float a, float b) {
    return h2u(gelu_fast(a), gelu_fast(b));
}

// -------- init: dtype detect + zero out --------
__global__ __launch_bounds__(256) void init_kernel(
    const int* __restrict__ ei32, float* __restrict__ out)
{
    int t = blockIdx.x * blockDim.x + threadIdx.x;
    if (blockIdx.x == 0 && threadIdx.x < 32) {
        int lane = threadIdx.x;
        int nz = (ei32[2 * lane + 1] != 0) || (ei32[2 * (lane + 32) + 1] != 0);
        unsigned any = __ballot_sync(0xffffffffu, nz);
        if (lane == 0) g_is64 = (any == 0u);
    }
    if (t < NPTS * 16) out[t] = 0.0f;
}

// -------- edge kernel: pipelined frag-chained MMA, 8 warp-tiles per CTA ----
__global__ __launch_bounds__(256, 2) void edge_kernel(
    const float* __restrict__ x, const float* __restrict__ pos,
    const int* __restrict__ ei,
    const float* __restrict__ W1, const float* __restrict__ b1,
    const float* __restrict__ bh, const float* __restrict__ Wh,
    const float* __restrict__ Wo, const float* __restrict__ bo,
    float* __restrict__ out)
{
    extern __shared__ char dyn[];
    __shared__ float sbh[64];
    __shared__ float sbo[256];
    __shared__ float sx[2][256 * 20];      // stride 20: float4-aligned, conflict-free
    __shared__ int   sdst[2][256];
    __shared__ __align__(16) uint4 spe[256];

    unsigned dbase = smem_u32(dyn);
    unsigned abase = (dbase + 1023u) & ~1023u;
    char* sp = dyn + (abase - dbase);
    const unsigned WH_OFF = 0, WO_OFF = 8192;
    unsigned WHs = abase + WH_OFF, WOs = abase + WO_OFF;

    int tid = threadIdx.x, lane = tid & 31, wid = tid >> 5;

    if (tid < 64) sbh[tid] = bh[tid];
    if (tid < 256) sbo[tid] = bo[tid];
    // WhT[c][j] = Wh[j*64+c]  fp16 K-major rows of 128B, SW128
    for (int t = tid; t < 4096; t += 256) {
        int j = t >> 6, c = t & 63;
        *(__half*)(sp + WH_OFF + SWZ(c * 128 + j * 2)) = __float2half_rn(Wh[t]);
    }
    // WoT[p][j] = Wo[j*256+p]
    for (int t = tid; t < 16384; t += 256) {
        int j = t >> 8, p = t & 255;
        *(__half*)(sp + WO_OFF + SWZ(p * 128 + j * 2)) = __float2half_rn(Wo[t]);
    }
    __syncthreads();

    const int is64 = g_is64;
    const int g = lane >> 2, tig = lane & 3;
    const int wb = wid * 32;
    const int row = wb + lane;

    // W1 B-frags (k8n8), bias folded as row 6 (pe[6]=1), row 7 = 0
    unsigned W1f[8];
    #pragma unroll
    for (int nt = 0; nt < 8; nt++) {
        int c = nt * 8 + g;
        W1f[nt] = (tig == 3) ? h2u(__ldg(&b1[c]), 0.0f)
                             : h2u(__ldg(&W1[(2 * tig) * 64 + c]),
                                   __ldg(&W1[(2 * tig + 1) * 64 + c]));
    }

    // hoisted swizzled B-address bases (1024-multiple row offsets add linearly)
    unsigned wh_a = WHs + SWZ((unsigned)(lane & 7) * 128 + (lane >> 3) * 16);
    unsigned wh_b = WHs + SWZ((unsigned)(lane & 7) * 128 + (4 + (lane >> 3)) * 16);
    unsigned wo_a = WOs + SWZ((unsigned)(lane & 7) * 128 + (lane >> 3) * 16);
    unsigned wo_b = WOs + SWZ((unsigned)(lane & 7) * 128 + (4 + (lane >> 3)) * 16);
    unsigned pe_addr = smem_u32(spe) + (unsigned)row * 16;

    int gw = blockIdx.x * 8 + wid;
    int nw = gridDim.x * 8;

    // ---- prologue: stage first tile into parity 0 ----
    {
        int e0 = gw * 32 + lane;
        int s0, d0i;
        if (is64) { s0 = ei[2 * e0]; d0i = ei[2 * NEDGE + 2 * e0]; }
        else      { s0 = ei[e0];     d0i = ei[NEDGE + e0]; }
        sdst[0][row] = d0i;
        uint4 pev;
        pev.x = h2u(__ldg(&pos[s0 * 3 + 0]), __ldg(&pos[s0 * 3 + 1]));
        pev.y = h2u(__ldg(&pos[s0 * 3 + 2]), __ldg(&pos[d0i * 3 + 0]));
        pev.z = h2u(__ldg(&pos[d0i * 3 + 1]), __ldg(&pos[d0i * 3 + 2]));
        pev.w = h2u(1.0f, 0.0f);
        spe[row] = pev;
        const float4* xp = (const float4*)(x + (size_t)s0 * 16);
        #pragma unroll
        for (int k2 = 0; k2 < 4; k2++)
            *(float4*)&sx[0][row * 20 + 4 * k2] = __ldg(xp + k2);
    }

    int p = 0;
    for (int t = gw; t < NWTILE; t += nw, p ^= 1) {
        int t2 = t + nw;
        const bool hn = (t2 < NWTILE);
        int pfs = 0, pfd = 0;
        if (hn) {   // prefetch next tile's indices (independent LDGs)
            int e2 = t2 * 32 + lane;
            if (is64) { pfs = ei[2 * e2]; pfd = ei[2 * NEDGE + 2 * e2]; }
            else      { pfs = ei[e2];     pfd = ei[NEDGE + e2]; }
        }
        __syncwarp();

        // ---- MMA1: h1 = gelu(pe @ [W1;b1;0]) ----
        unsigned pA0, pA1, pA2, pA3;
        LDSM4(pA0, pA1, pA2, pA3, pe_addr);

        unsigned h1f[2][4][4];
        #pragma unroll
        for (int kc = 0; kc < 4; kc++)
            #pragma unroll
            for (int par = 0; par < 2; par++) {
                unsigned b = W1f[2 * kc + par];
                #pragma unroll
                for (int mt = 0; mt < 2; mt++) {
                    float d[4] = {0.0f, 0.0f, 0.0f, 0.0f};
                    MMA16808(d, mt ? pA2 : pA0, mt ? pA3 : pA1, b);
                    h1f[mt][kc][2 * par]     = gelu2_pack(d[0], d[1]);
                    h1f[mt][kc][2 * par + 1] = gelu2_pack(d[2], d[3]);
                }
            }

        // ---- stage next tile (phase 1): indices arrived; issue pos/x LDGs ----
        float pp0, pp1, pp2, pp3, pp4, pp5;
        float4 xv0, xv1, xv2, xv3;
        if (hn) {
            sdst[p ^ 1][row] = pfd;
            pp0 = __ldg(&pos[pfs * 3 + 0]); pp1 = __ldg(&pos[pfs * 3 + 1]);
            pp2 = __ldg(&pos[pfs * 3 + 2]);
            pp3 = __ldg(&pos[pfd * 3 + 0]); pp4 = __ldg(&pos[pfd * 3 + 1]);
            pp5 = __ldg(&pos[pfd * 3 + 2]);
            const float4* xp2 = (const float4*)(x + (size_t)pfs * 16);
            xv0 = __ldg(xp2 + 0); xv1 = __ldg(xp2 + 1);
            xv2 = __ldg(xp2 + 2); xv3 = __ldg(xp2 + 3);
        }

        // ---- MMA2: h2 = gelu(h1 @ Wh + bh), split accumulator chains ----
        unsigned h2f[2][4][4];
        #pragma unroll
        for (int kc = 0; kc < 4; kc++)
            #pragma unroll
            for (int par = 0; par < 2; par++) {
                int nt = 2 * kc + par;
                unsigned b0, b1r, b2, b3, b4, b5, b6, b7;
                LDSM4(b0, b1r, b2, b3, wh_a + (unsigned)nt * 1024);
                LDSM4(b4, b5, b6, b7, wh_b + (unsigned)nt * 1024);
                float2 bh2 = *(const float2*)&sbh[nt * 8 + 2 * tig];
                #pragma unroll
                for (int mt = 0; mt < 2; mt++) {
                    float d[4]  = {bh2.x, bh2.y, bh2.x, bh2.y};
                    float d2[4] = {0.0f, 0.0f, 0.0f, 0.0f};
                    MMA16816(d,  h1f[mt][0][0], h1f[mt][0][1], h1f[mt][0][2], h1f[mt][0][3], b0, b1r);
                    MMA16816(d2, h1f[mt][1][0], h1f[mt][1][1], h1f[mt][1][2], h1f[mt][1][3], b2, b3);
                    MMA16816(d,  h1f[mt][2][0], h1f[mt][2][1], h1f[mt][2][2], h1f[mt][2][3], b4, b5);
                    MMA16816(d2, h1f[mt][3][0], h1f[mt][3][1], h1f[mt][3][2], h1f[mt][3][3], b6, b7);
                    h2f[mt][kc][2 * par]     = gelu2_pack(d[0] + d2[0], d[1] + d2[1]);
                    h2f[mt][kc][2 * par + 1] = gelu2_pack(d[2] + d2[2], d[3] + d2[3]);
                }
            }

        // ---- stage next tile (phase 2): store pos/x (frees regs before MMA3) ----
        if (hn) {
            uint4 pev;
            pev.x = h2u(pp0, pp1); pev.y = h2u(pp2, pp3);
            pev.z = h2u(pp4, pp5); pev.w = h2u(1.0f, 0.0f);
            spe[row] = pev;        // safe: this tile's pe LDSM (collective) already done
            float* sxr = &sx[p ^ 1][row * 20];
            *(float4*)(sxr + 0)  = xv0; *(float4*)(sxr + 4)  = xv1;
            *(float4*)(sxr + 8)  = xv2; *(float4*)(sxr + 12) = xv3;
        }

        // ---- MMA3: z = h2 @ Wo + bo (bias in accum init); fold x-contraction ----
        const float* sxp = &sx[p][0];
        float msg[16];
        #pragma unroll
        for (int q = 0; q < 16; q++) msg[q] = 0.0f;

        #pragma unroll
        for (int ch = 0; ch < 4; ch++) {
            #pragma unroll
            for (int ntp = 0; ntp < 4; ntp++) {
                unsigned prow0 = (unsigned)(ch * 64 + (2 * ntp) * 8) * 128;
                unsigned prow1 = prow0 + 1024;
                unsigned b0, b1r, b2, b3, b4, b5, b6, b7;
                unsigned c0, c1r, c2, c3, c4, c5, c6, c7;
                LDSM4(b0, b1r, b2, b3, wo_a + prow0);
                LDSM4(b4, b5, b6, b7, wo_b + prow0);
                LDSM4(c0, c1r, c2, c3, wo_a + prow1);
                LDSM4(c4, c5, c6, c7, wo_b + prow1);
                int i = 4 * ch + ntp;
                int cbase = ch * 64 + ntp * 16 + 2 * tig;          // col of d0[0]
                float2 bz0 = *(const float2*)&sbo[cbase];
                float2 bz1 = *(const float2*)&sbo[cbase + 8];
                #pragma unroll
                for (int mt = 0; mt < 2; mt++) {
                    int r1 = wb + mt * 16 + g;
                    float xa = sxp[r1 * 20 + i];
                    float xb = sxp[(r1 + 8) * 20 + i];
                    float d0[4] = {bz0.x, bz0.y, bz0.x, bz0.y};
                    float d1[4] = {bz1.x, bz1.y, bz1.x, bz1.y};
                    MMA16816(d0, h2f[mt][0][0], h2f[mt][0][1], h2f[mt][0][2], h2f[mt][0][3], b0, b1r);
                    MMA16816(d1, h2f[mt][0][0], h2f[mt][0][1], h2f[mt][0][2], h2f[mt][0][3], c0, c1r);
                    MMA16816(d0, h2f[mt][1][0], h2f[mt][1][1], h2f[mt][1][2], h2f[mt][1][3], b2, b3);
                    MMA16816(d1, h2f[mt][1][0], h2f[mt][1][1], h2f[mt][1][2], h2f[mt][1][3], c2, c3);
                    MMA16816(d0, h2f[mt][2][0], h2f[mt][2][1], h2f[mt][2][2], h2f[mt][2][3], b4, b5);
                    MMA16816(d1, h2f[mt][2][0], h2f[mt][2][1], h2f[mt][2][2], h2f[mt][2][3], c4, c5);
                    MMA16816(d0, h2f[mt][3][0], h2f[mt][3][1], h2f[mt][3][2], h2f[mt][3][3], b6, b7);
                    MMA16816(d1, h2f[mt][3][0], h2f[mt][3][1], h2f[mt][3][2], h2f[mt][3][3], c6, c7);
                    msg[(mt * 2 + 0) * 4 + 0] += d0[0] * xa;
                    msg[(mt * 2 + 0) * 4 + 1] += d0[1] * xa;
                    msg[(mt * 2 + 1) * 4 + 0] += d0[2] * xb;
                    msg[(mt * 2 + 1) * 4 + 1] += d0[3] * xb;
                    msg[(mt * 2 + 0) * 4 + 2] += d1[0] * xa;
                    msg[(mt * 2 + 0) * 4 + 3] += d1[1] * xa;
                    msg[(mt * 2 + 1) * 4 + 2] += d1[2] * xb;
                    msg[(mt * 2 + 1) * 4 + 3] += d1[3] * xb;
                }
            }
        }

        // ---- scatter: each (row,o) owned by exactly one lane ----
        #pragma unroll
        for (int mr = 0; mr < 4; mr++) {
            int row_ = wb + (mr >> 1) * 16 + g + (mr & 1) * 8;
            int d_ = sdst[p][row_];
            #pragma unroll
            for (int q = 0; q < 4; q++) {
                int o = (q >> 1) * 8 + 2 * tig + (q & 1);
                atomicAdd(out + (size_t)d_ * 16 + o, msg[mr * 4 + q]);
            }
        }
    }
}

extern "C" void kernel_launch(void* const* d_in, const int* in_sizes, int n_in,
                              void* d_out, int out_size) {
    const float* x   = (const float*)d_in[0];
    const float* pos = (const float*)d_in[1];
    const int*   ei  = (const int*)d_in[2];
    const float* W1  = (const float*)d_in[3];
    const float* b1  = (const float*)d_in[4];
    const float* Wh  = (const float*)d_in[5];
    const float* bh  = (const float*)d_in[6];
    const float* Wo  = (const float*)d_in[7];
    const float* bo  = (const float*)d_in[8];
    float* out = (float*)d_out;

    cudaFuncSetAttribute(edge_kernel, cudaFuncAttributeMaxDynamicSharedMemorySize, 41984);

    init_kernel<<<(NPTS * 16 + 255) / 256, 256>>>(ei, out);
    edge_kernel<<<296, 256, 41984>>>(x, pos, ei, W1, b1, bh, Wh, Wo, bo, out);
}

// round 13
// speedup vs baseline: 12.0586x; 1.0799x over previous
#include <cuda_runtime.h>
#include <cuda_fp16.h>

#define NPTS   50000
#define NEDGE  800000
#define NT16   50000      // 16 edges per warp-tile

__device__ int g_is64;

#define SWZ(b) ((b) ^ (((b) >> 3) & 0x70))

__device__ __forceinline__ unsigned smem_u32(const void* p) {
    unsigned a;
    asm("{ .reg .u64 t; cvta.to.shared.u64 t, %1; cvt.u32.u64 %0, t; }" : "=r"(a) : "l"(p));
    return a;
}

#define LDSM2(r0, r1, addr) \
    asm volatile("ldmatrix.sync.aligned.m8n8.x2.shared.b16 {%0,%1}, [%2];" \
        : "=r"(r0), "=r"(r1) : "r"(addr))

#define LDSM4(r0, r1, r2, r3, addr) \
    asm volatile("ldmatrix.sync.aligned.m8n8.x4.shared.b16 {%0,%1,%2,%3}, [%4];" \
        : "=r"(r0), "=r"(r1), "=r"(r2), "=r"(r3) : "r"(addr))

#define MMA16816(d, a0, a1, a2, a3, b0, b1) \
    asm volatile("mma.sync.aligned.m16n8k16.row.col.f32.f16.f16.f32 " \
        "{%0,%1,%2,%3}, {%4,%5,%6,%7}, {%8,%9}, {%0,%1,%2,%3};" \
        : "+f"((d)[0]), "+f"((d)[1]), "+f"((d)[2]), "+f"((d)[3]) \
        : "r"(a0), "r"(a1), "r"(a2), "r"(a3), "r"(b0), "r"(b1))

#define MMA16808(d, a0, a1, b0) \
    asm volatile("mma.sync.aligned.m16n8k8.row.col.f32.f16.f16.f32 " \
        "{%0,%1,%2,%3}, {%4,%5}, {%6}, {%0,%1,%2,%3};" \
        : "+f"((d)[0]), "+f"((d)[1]), "+f"((d)[2]), "+f"((d)[3]) \
        : "r"(a0), "r"(a1), "r"(b0))

#define CP_ASYNC16(smem, gmem) \
    asm volatile("cp.async.ca.shared.global [%0], [%1], 16;" \
        :: "r"(smem), "l"(gmem) : "memory")
#define CP_COMMIT() asm volatile("cp.async.commit_group;" ::: "memory")

// Branchless gelu, erf via A-S 7.1.25 (3-term, |eps|<=2.5e-5, far below fp16 rounding).
__device__ __forceinline__ float gelu_fast(float x) {
    float t = fabsf(x) * 0.70710678118654752440f;
    float k = __fdividef(1.0f, fmaf(0.47047f, t, 1.0f));
    float p = fmaf(fmaf(0.7478556f, k, -0.0958798f), k, 0.3480242f) * k;
    float e = __expf(-t * t);
    float erf = fmaf(-p, e, 1.0f);
    float phi = fmaf(copysignf(erf, x), 0.5f, 0.5f);
    return x * phi;
}
__device__ __forceinline__ unsigned h2u(float a, float b) {
    __half2 h = __floats2half2_rn(a, b);
    return *(unsigned*)&h;
}
__device__ __forceinline__ unsigned gelu2_pack(float a, float b) {
    return h2u(gelu_fast(a), gelu_fast(b));
}

// -------- init: dtype detect + zero out --------
__global__ __launch_bounds__(256) void init_kernel(
    const int* __restrict__ ei32, float* __restrict__ out)
{
    int t = blockIdx.x * blockDim.x + threadIdx.x;
    if (blockIdx.x == 0 && threadIdx.x < 32) {
        int lane = threadIdx.x;
        int nz = (ei32[2 * lane + 1] != 0) || (ei32[2 * (lane + 32) + 1] != 0);
        unsigned any = __ballot_sync(0xffffffffu, nz);
        if (lane == 0) g_is64 = (any == 0u);
    }
    if (t < NPTS * 16) out[t] = 0.0f;
}

// -------- edge kernel: m16 warp-tiles, 3 CTAs/SM, cp.async x-prefetch ----
__global__ __launch_bounds__(256, 3) void edge_kernel(
    const float* __restrict__ x, const float* __restrict__ pos,
    const int* __restrict__ ei,
    const float* __restrict__ W1, const float* __restrict__ b1,
    const float* __restrict__ bh, const float* __restrict__ Wh,
    const float* __restrict__ Wo, const float* __restrict__ bo,
    float* __restrict__ out)
{
    extern __shared__ char dyn[];
    __shared__ float sbh[64];
    __shared__ float sbo[256];
    __shared__ unsigned sW1f[8 * 32];
    __shared__ float sx[2][128 * 20];      // fp32 x, stride 20 (conflict-free, 16B-aligned)
    __shared__ int   sdst[2][128];
    __shared__ __align__(16) uint4 spe[128];

    unsigned dbase = smem_u32(dyn);
    unsigned abase = (dbase + 1023u) & ~1023u;
    char* sp = dyn + (abase - dbase);
    const unsigned WH_OFF = 0, WO_OFF = 8192;
    unsigned WHs = abase + WH_OFF, WOs = abase + WO_OFF;

    int tid = threadIdx.x, lane = tid & 31, wid = tid >> 5;
    const unsigned F = 0xffffffffu;

    if (tid < 64) sbh[tid] = bh[tid];
    if (tid < 256) sbo[tid] = bo[tid];
    if (tid < 32) {      // W1 B-frags (k8n8), bias folded as row 6 (pe[6]=1), row 7 = 0
        int lg = tid >> 2, ltig = tid & 3;
        #pragma unroll
        for (int nt = 0; nt < 8; nt++) {
            int c = nt * 8 + lg;
            sW1f[nt * 32 + tid] = (ltig == 3)
                ? h2u(__ldg(&b1[c]), 0.0f)
                : h2u(__ldg(&W1[(2 * ltig) * 64 + c]), __ldg(&W1[(2 * ltig + 1) * 64 + c]));
        }
    }
    // WhT[c][j] = Wh[j*64+c]  fp16 K-major rows of 128B, SW128
    for (int t = tid; t < 4096; t += 256) {
        int j = t >> 6, c = t & 63;
        *(__half*)(sp + WH_OFF + SWZ(c * 128 + j * 2)) = __float2half_rn(Wh[t]);
    }
    // WoT[p][j] = Wo[j*256+p]
    for (int t = tid; t < 16384; t += 256) {
        int j = t >> 8, p = t & 255;
        *(__half*)(sp + WO_OFF + SWZ(p * 128 + j * 2)) = __float2half_rn(Wo[t]);
    }
    __syncthreads();

    const int is64 = g_is64;
    const int g = lane >> 2, tig = lane & 3;
    const int wb = wid * 16;
    const int er = lane & 15;               // edge slot within tile
    const int xrow = lane >> 1, xh = lane & 1;   // x staging: 2 lanes per row

    // hoisted swizzled B-address bases (1024-multiple row offsets add linearly)
    unsigned wh_a = WHs + SWZ((unsigned)(lane & 7) * 128 + (lane >> 3) * 16);
    unsigned wh_b = WHs + SWZ((unsigned)(lane & 7) * 128 + (4 + (lane >> 3)) * 16);
    unsigned wo_a = WOs + SWZ((unsigned)(lane & 7) * 128 + (lane >> 3) * 16);
    unsigned wo_b = WOs + SWZ((unsigned)(lane & 7) * 128 + (4 + (lane >> 3)) * 16);
    unsigned pe_addr = smem_u32(spe) + (unsigned)(wb + er) * 16;
    unsigned sx_u = smem_u32(sx);

    int gw = blockIdx.x * 8 + wid;
    int nw = gridDim.x * 8;

    // ---- prologue: stage tile gw into parity 0 ----
    {
        int e0 = gw * 16 + er;
        int s0, d0i;
        if (is64) { s0 = ei[2 * e0]; d0i = ei[2 * NEDGE + 2 * e0]; }
        else      { s0 = ei[e0];     d0i = ei[NEDGE + e0]; }
        sdst[0][wb + er] = d0i;
        uint4 pev;
        pev.x = h2u(__ldg(&pos[s0 * 3 + 0]), __ldg(&pos[s0 * 3 + 1]));
        pev.y = h2u(__ldg(&pos[s0 * 3 + 2]), __ldg(&pos[d0i * 3 + 0]));
        pev.z = h2u(__ldg(&pos[d0i * 3 + 1]), __ldg(&pos[d0i * 3 + 2]));
        pev.w = h2u(1.0f, 0.0f);
        spe[wb + er] = pev;
        int s2 = __shfl_sync(F, s0, xrow);
        const char* gx = (const char*)(x + (size_t)s2 * 16 + xh * 8);
        unsigned sa = sx_u + (unsigned)((wb + xrow) * 20 + xh * 8) * 4;
        CP_ASYNC16(sa, gx);
        CP_ASYNC16(sa + 16, gx + 16);
        CP_COMMIT();
    }

    int p = 0;
    for (int t = gw; t < NT16; t += nw, p ^= 1) {
        int t2 = t + nw;
        const bool hn = (t2 < NT16);
        int pfs = 0, pfd = 0;
        if (hn) {
            int e2 = t2 * 16 + er;
            if (is64) { pfs = ei[2 * e2]; pfd = ei[2 * NEDGE + 2 * e2]; }
            else      { pfs = ei[e2];     pfd = ei[NEDGE + e2]; }
        }
        __syncwarp();

        // ---- MMA1: h1 = gelu(pe @ [W1;b1;0]) ----
        unsigned pA0, pA1;
        LDSM2(pA0, pA1, pe_addr);

        unsigned h1f[4][4];
        #pragma unroll
        for (int kc = 0; kc < 4; kc++)
            #pragma unroll
            for (int par = 0; par < 2; par++) {
                unsigned b = sW1f[(2 * kc + par) * 32 + lane];
                float d[4] = {0.0f, 0.0f, 0.0f, 0.0f};
                MMA16808(d, pA0, pA1, b);
                h1f[kc][2 * par]     = gelu2_pack(d[0], d[1]);
                h1f[kc][2 * par + 1] = gelu2_pack(d[2], d[3]);
            }

        // ---- stage next tile (phase 1): pos LDGs + x via cp.async ----
        float pp0, pp1, pp2, pp3, pp4, pp5;
        if (hn) {
            sdst[p ^ 1][wb + er] = pfd;
            pp0 = __ldg(&pos[pfs * 3 + 0]); pp1 = __ldg(&pos[pfs * 3 + 1]);
            pp2 = __ldg(&pos[pfs * 3 + 2]);
            pp3 = __ldg(&pos[pfd * 3 + 0]); pp4 = __ldg(&pos[pfd * 3 + 1]);
            pp5 = __ldg(&pos[pfd * 3 + 2]);
            int s2 = __shfl_sync(F, pfs, xrow);
            const char* gx = (const char*)(x + (size_t)s2 * 16 + xh * 8);
            unsigned sa = sx_u + (unsigned)((p ^ 1) * 2560 + (wb + xrow) * 20 + xh * 8) * 4;
            CP_ASYNC16(sa, gx);
            CP_ASYNC16(sa + 16, gx + 16);
            CP_COMMIT();
        }

        // ---- MMA2: h2 = gelu(h1 @ Wh + bh), split accumulator chains ----
        unsigned h2f[4][4];
        #pragma unroll
        for (int kc = 0; kc < 4; kc++)
            #pragma unroll
            for (int par = 0; par < 2; par++) {
                int nt = 2 * kc + par;
                unsigned b0, b1r, b2, b3, b4, b5, b6, b7;
                LDSM4(b0, b1r, b2, b3, wh_a + (unsigned)nt * 1024);
                LDSM4(b4, b5, b6, b7, wh_b + (unsigned)nt * 1024);
                float2 bh2 = *(const float2*)&sbh[nt * 8 + 2 * tig];
                float d[4]  = {bh2.x, bh2.y, bh2.x, bh2.y};
                float d2[4] = {0.0f, 0.0f, 0.0f, 0.0f};
                MMA16816(d,  h1f[0][0], h1f[0][1], h1f[0][2], h1f[0][3], b0, b1r);
                MMA16816(d2, h1f[1][0], h1f[1][1], h1f[1][2], h1f[1][3], b2, b3);
                MMA16816(d,  h1f[2][0], h1f[2][1], h1f[2][2], h1f[2][3], b4, b5);
                MMA16816(d2, h1f[3][0], h1f[3][1], h1f[3][2], h1f[3][3], b6, b7);
                h2f[kc][2 * par]     = gelu2_pack(d[0] + d2[0], d[1] + d2[1]);
                h2f[kc][2 * par + 1] = gelu2_pack(d[2] + d2[2], d[3] + d2[3]);
            }

        // ---- stage next tile (phase 2): pack + store pe ----
        if (hn) {
            uint4 pev;
            pev.x = h2u(pp0, pp1); pev.y = h2u(pp2, pp3);
            pev.z = h2u(pp4, pp5); pev.w = h2u(1.0f, 0.0f);
            spe[wb + er] = pev;    // safe: this tile's pe LDSM already done
        }

        // ---- wait for this tile's x (issued last iteration / prologue) ----
        if (hn) { asm volatile("cp.async.wait_group 1;" ::: "memory"); }
        else    { asm volatile("cp.async.wait_group 0;" ::: "memory"); }
        __syncwarp();

        // ---- MMA3: z = h2 @ Wo + bo; fold x-contraction ----
        const float* sxp = &sx[p][0];
        float msg[8];
        #pragma unroll
        for (int q = 0; q < 8; q++) msg[q] = 0.0f;

        #pragma unroll
        for (int ch = 0; ch < 4; ch++) {
            #pragma unroll
            for (int ntp = 0; ntp < 4; ntp++) {
                unsigned prow0 = (unsigned)(ch * 64 + ntp * 16) * 128;
                unsigned prow1 = prow0 + 1024;
                unsigned b0, b1r, b2, b3, b4, b5, b6, b7;
                unsigned c0, c1r, c2, c3, c4, c5, c6, c7;
                LDSM4(b0, b1r, b2, b3, wo_a + prow0);
                LDSM4(b4, b5, b6, b7, wo_b + prow0);
                LDSM4(c0, c1r, c2, c3, wo_a + prow1);
                LDSM4(c4, c5, c6, c7, wo_b + prow1);
                int i = 4 * ch + ntp;
                int cbase = ch * 64 + ntp * 16 + 2 * tig;
                float2 bz0 = *(const float2*)&sbo[cbase];
                float2 bz1 = *(const float2*)&sbo[cbase + 8];
                float xa = sxp[(wb + g) * 20 + i];
                float xb = sxp[(wb + g + 8) * 20 + i];
                float d0[4] = {bz0.x, bz0.y, bz0.x, bz0.y};
                float d1[4] = {bz1.x, bz1.y, bz1.x, bz1.y};
                MMA16816(d0, h2f[0][0], h2f[0][1], h2f[0][2], h2f[0][3], b0, b1r);
                MMA16816(d1, h2f[0][0], h2f[0][1], h2f[0][2], h2f[0][3], c0, c1r);
                MMA16816(d0, h2f[1][0], h2f[1][1], h2f[1][2], h2f[1][3], b2, b3);
                MMA16816(d1, h2f[1][0], h2f[1][1], h2f[1][2], h2f[1][3], c2, c3);
                MMA16816(d0, h2f[2][0], h2f[2][1], h2f[2][2], h2f[2][3], b4, b5);
                MMA16816(d1, h2f[2][0], h2f[2][1], h2f[2][2], h2f[2][3], c4, c5);
                MMA16816(d0, h2f[3][0], h2f[3][1], h2f[3][2], h2f[3][3], b6, b7);
                MMA16816(d1, h2f[3][0], h2f[3][1], h2f[3][2], h2f[3][3], c6, c7);
                msg[0] += d0[0] * xa;  msg[1] += d0[1] * xa;
                msg[4] += d0[2] * xb;  msg[5] += d0[3] * xb;
                msg[2] += d1[0] * xa;  msg[3] += d1[1] * xa;
                msg[6] += d1[2] * xb;  msg[7] += d1[3] * xb;
            }
        }

        // ---- scatter: rows g and g+8, 4 cols each ----
        int dA = sdst[p][wb + g];
        int dB = sdst[p][wb + g + 8];
        #pragma unroll
        for (int q = 0; q < 4; q++) {
            int o = (q >> 1) * 8 + 2 * tig + (q & 1);
            atomicAdd(out + (size_t)dA * 16 + o, msg[q]);
            atomicAdd(out + (size_t)dB * 16 + o, msg[4 + q]);
        }
    }
}

extern "C" void kernel_launch(void* const* d_in, const int* in_sizes, int n_in,
                              void* d_out, int out_size) {
    const float* x   = (const float*)d_in[0];
    const float* pos = (const float*)d_in[1];
    const int*   ei  = (const int*)d_in[2];
    const float* W1  = (const float*)d_in[3];
    const float* b1  = (const float*)d_in[4];
    const float* Wh  = (const float*)d_in[5];
    const float* bh  = (const float*)d_in[6];
    const float* Wo  = (const float*)d_in[7];
    const float* bo  = (const float*)d_in[8];
    float* out = (float*)d_out;

    cudaFuncSetAttribute(edge_kernel, cudaFuncAttributeMaxDynamicSharedMemorySize, 41984);

    init_kernel<<<(NPTS * 16 + 255) / 256, 256>>>(ei, out);
    edge_kernel<<<444, 256, 41984>>>(x, pos, ei, W1, b1, bh, Wh, Wo, bo, out);
}

// round 15
// speedup vs baseline: 12.3650x; 1.0254x over previous
#include <cuda_runtime.h>
#include <cuda_fp16.h>

#define NPTS   50000
#define NEDGE  800000
#define NT16   50000      // 16 edges per warp-tile
#define GRID   444
#define NWTOT  (GRID * 8)         // 3552 warps
#define KSTAT  14                 // static tiles per warp
#define TAIL0  (NWTOT * KSTAT)    // 49728

__device__ int g_is64;
__device__ int g_tailctr;

#define SWZ(b) ((b) ^ (((b) >> 3) & 0x70))

__device__ __forceinline__ unsigned smem_u32(const void* p) {
    unsigned a;
    asm("{ .reg .u64 t; cvta.to.shared.u64 t, %1; cvt.u32.u64 %0, t; }" : "=r"(a) : "l"(p));
    return a;
}

#define LDSM2(r0, r1, addr) \
    asm volatile("ldmatrix.sync.aligned.m8n8.x2.shared.b16 {%0,%1}, [%2];" \
        : "=r"(r0), "=r"(r1) : "r"(addr))

#define LDSM4(r0, r1, r2, r3, addr) \
    asm volatile("ldmatrix.sync.aligned.m8n8.x4.shared.b16 {%0,%1,%2,%3}, [%4];" \
        : "=r"(r0), "=r"(r1), "=r"(r2), "=r"(r3) : "r"(addr))

#define MMA16816(d, a0, a1, a2, a3, b0, b1) \
    asm volatile("mma.sync.aligned.m16n8k16.row.col.f32.f16.f16.f32 " \
        "{%0,%1,%2,%3}, {%4,%5,%6,%7}, {%8,%9}, {%0,%1,%2,%3};" \
        : "+f"((d)[0]), "+f"((d)[1]), "+f"((d)[2]), "+f"((d)[3]) \
        : "r"(a0), "r"(a1), "r"(a2), "r"(a3), "r"(b0), "r"(b1))

#define MMA16808(d, a0, a1, b0) \
    asm volatile("mma.sync.aligned.m16n8k8.row.col.f32.f16.f16.f32 " \
        "{%0,%1,%2,%3}, {%4,%5}, {%6}, {%0,%1,%2,%3};" \
        : "+f"((d)[0]), "+f"((d)[1]), "+f"((d)[2]), "+f"((d)[3]) \
        : "r"(a0), "r"(a1), "r"(b0))

#define CP_ASYNC16(smem, gmem) \
    asm volatile("cp.async.ca.shared.global [%0], [%1], 16;" \
        :: "r"(smem), "l"(gmem) : "memory")
#define CP_COMMIT() asm volatile("cp.async.commit_group;" ::: "memory")

__device__ __forceinline__ unsigned h2u(float a, float b) {
    __half2 h = __floats2half2_rn(a, b);
    return *(unsigned*)&h;
}

__device__ __forceinline__ unsigned long long dup2f(float f) {
    unsigned u = __float_as_uint(f);
    return ((unsigned long long)u << 32) | (unsigned long long)u;
}

// Packed-f32x2 branchless gelu pair -> half2 bits.
// erf via A-S 7.1.25 (|eps|<=2.5e-5, << fp16 rounding), sign handled by
// res = 0.5*[(x+|x|) - |x|*(p~*e)] with negated poly (p~ = -P(k)), e = exp(-x^2/2).
__device__ __forceinline__ unsigned gelu2_pack(float a, float b) {
    unsigned long long vx, va, vq, vk, vp, vs;
    float q0, q1;
    asm("mov.b64 %0, {%1, %2};" : "=l"(vx) : "f"(a), "f"(b));
    va = vx & 0x7FFFFFFF7FFFFFFFULL;                                   // |x|
    asm("fma.rn.f32x2 %0, %1, %2, %3;" : "=l"(vq)
        : "l"(va), "l"(dup2f(0.33268194f)), "l"(dup2f(1.0f)));         // 1 + 0.47047*|x|/sqrt2
    asm("mov.b64 {%0, %1}, %2;" : "=f"(q0), "=f"(q1) : "l"(vq));
    asm("rcp.approx.f32 %0, %1;" : "=f"(q0) : "f"(q0));
    asm("rcp.approx.f32 %0, %1;" : "=f"(q1) : "f"(q1));
    asm("mov.b64 %0, {%1, %2};" : "=l"(vk) : "f"(q0), "f"(q1));        // k
    asm("fma.rn.f32x2 %0, %1, %2, %3;" : "=l"(vp)
        : "l"(vk), "l"(dup2f(-0.7478556f)), "l"(dup2f(0.0958798f)));
    asm("fma.rn.f32x2 %0, %1, %2, %3;" : "=l"(vp)
        : "l"(vp), "l"(vk), "l"(dup2f(-0.3480242f)));
    asm("mul.rn.f32x2 %0, %1, %2;" : "=l"(vp) : "l"(vp), "l"(vk));     // -P(k)
    asm("mul.rn.f32x2 %0, %1, %2;" : "=l"(vq) : "l"(vx), "l"(vx));     // x^2
    asm("mul.rn.f32x2 %0, %1, %2;" : "=l"(vq)
        : "l"(vq), "l"(dup2f(-0.72134752f)));                          // -x^2*log2e/2
    asm("mov.b64 {%0, %1}, %2;" : "=f"(q0), "=f"(q1) : "l"(vq));
    asm("ex2.approx.f32 %0, %1;" : "=f"(q0) : "f"(q0));
    asm("ex2.approx.f32 %0, %1;" : "=f"(q1) : "f"(q1));
    asm("mov.b64 %0, {%1, %2};" : "=l"(vq) : "f"(q0), "f"(q1));        // exp(-x^2/2)
    asm("mul.rn.f32x2 %0, %1, %2;" : "=l"(vp) : "l"(vp), "l"(vq));     // -P*e
    asm("add.rn.f32x2 %0, %1, %2;" : "=l"(vs) : "l"(vx), "l"(va));     // x+|x|
    asm("fma.rn.f32x2 %0, %1, %2, %3;" : "=l"(vs) : "l"(va), "l"(vp), "l"(vs));
    asm("mul.rn.f32x2 %0, %1, %2;" : "=l"(vs) : "l"(vs), "l"(dup2f(0.5f)));
    asm("mov.b64 {%0, %1}, %2;" : "=f"(q0), "=f"(q1) : "l"(vs));
    unsigned r;
    asm("cvt.rn.f16x2.f32 %0, %1, %2;" : "=r"(r) : "f"(q1), "f"(q0));  // {lo=g(a), hi=g(b)}
    return r;
}

// -------- init: dtype detect + zero out + tail counter reset --------
__global__ __launch_bounds__(256) void init_kernel(
    const int* __restrict__ ei32, float* __restrict__ out)
{
    int t = blockIdx.x * blockDim.x + threadIdx.x;
    if (blockIdx.x == 0 && threadIdx.x < 32) {
        int lane = threadIdx.x;
        int nz = (ei32[2 * lane + 1] != 0) || (ei32[2 * (lane + 32) + 1] != 0);
        unsigned any = __ballot_sync(0xffffffffu, nz);
        if (lane == 0) g_is64 = (any == 0u);
    }
    if (blockIdx.x == 0 && threadIdx.x == 32) g_tailctr = TAIL0;
    if (t < NPTS * 16) out[t] = 0.0f;
}

// -------- edge kernel: m16 warp-tiles, 3 CTAs/SM, cp.async prefetch, tail pool ----
__global__ __launch_bounds__(256, 3) void edge_kernel(
    const float* __restrict__ x, const float* __restrict__ pos,
    const int* __restrict__ ei,
    const float* __restrict__ W1, const float* __restrict__ b1,
    const float* __restrict__ bh, const float* __restrict__ Wh,
    const float* __restrict__ Wo, const float* __restrict__ bo,
    float* __restrict__ out)
{
    extern __shared__ char dyn[];
    __shared__ float sbh[64];
    __shared__ float sbo[256];
    __shared__ unsigned sW1f[8 * 32];
    __shared__ float sx[2][128 * 20];      // fp32 x, stride 20 (conflict-free, 16B-aligned)
    __shared__ int   sdst[2][128];
    __shared__ __align__(16) uint4 spe[128];

    unsigned dbase = smem_u32(dyn);
    unsigned abase = (dbase + 1023u) & ~1023u;
    char* sp = dyn + (abase - dbase);
    const unsigned WH_OFF = 0, WO_OFF = 8192;
    unsigned WHs = abase + WH_OFF, WOs = abase + WO_OFF;

    int tid = threadIdx.x, lane = tid & 31, wid = tid >> 5;
    const unsigned F = 0xffffffffu;

    if (tid < 64) sbh[tid] = bh[tid];
    if (tid < 256) sbo[tid] = bo[tid];
    if (tid < 32) {      // W1 B-frags (k8n8), bias folded as row 6 (pe[6]=1), row 7 = 0
        int lg = tid >> 2, ltig = tid & 3;
        #pragma unroll
        for (int nt = 0; nt < 8; nt++) {
            int c = nt * 8 + lg;
            sW1f[nt * 32 + tid] = (ltig == 3)
                ? h2u(__ldg(&b1[c]), 0.0f)
                : h2u(__ldg(&W1[(2 * ltig) * 64 + c]), __ldg(&W1[(2 * ltig + 1) * 64 + c]));
        }
    }
    // WhT[c][j] = Wh[j*64+c]  fp16 K-major rows of 128B, SW128
    for (int t = tid; t < 4096; t += 256) {
        int j = t >> 6, c = t & 63;
        *(__half*)(sp + WH_OFF + SWZ(c * 128 + j * 2)) = __float2half_rn(Wh[t]);
    }
    // WoT[p][j] = Wo[j*256+p]
    for (int t = tid; t < 16384; t += 256) {
        int j = t >> 8, p = t & 255;
        *(__half*)(sp + WO_OFF + SWZ(p * 128 + j * 2)) = __float2half_rn(Wo[t]);
    }
    __syncthreads();

    const int is64 = g_is64;
    const int g = lane >> 2, tig = lane & 3;
    const int wb = wid * 16;
    const int er = lane & 15;               // edge slot within tile
    const int xrow = lane >> 1, xh = lane & 1;   // x staging: 2 lanes per row

    // hoisted swizzled B-address bases (1024-multiple row offsets add linearly)
    unsigned wh_a = WHs + SWZ((unsigned)(lane & 7) * 128 + (lane >> 3) * 16);
    unsigned wh_b = WHs + SWZ((unsigned)(lane & 7) * 128 + (4 + (lane >> 3)) * 16);
    unsigned wo_a = WOs + SWZ((unsigned)(lane & 7) * 128 + (lane >> 3) * 16);
    unsigned wo_b = WOs + SWZ((unsigned)(lane & 7) * 128 + (4 + (lane >> 3)) * 16);
    unsigned pe_addr = smem_u32(spe) + (unsigned)(wb + er) * 16;
    unsigned sx_u = smem_u32(sx);

    int gw = blockIdx.x * 8 + wid;
    int nw = NWTOT;

    // ---- prologue: stage tile gw into parity 0 ----
    {
        int e0 = gw * 16 + er;
        int s0, d0i;
        if (is64) { s0 = ei[2 * e0]; d0i = ei[2 * NEDGE + 2 * e0]; }
        else      { s0 = ei[e0];     d0i = ei[NEDGE + e0]; }
        sdst[0][wb + er] = d0i;
        uint4 pev;
        pev.x = h2u(__ldg(&pos[s0 * 3 + 0]), __ldg(&pos[s0 * 3 + 1]));
        pev.y = h2u(__ldg(&pos[s0 * 3 + 2]), __ldg(&pos[d0i * 3 + 0]));
        pev.z = h2u(__ldg(&pos[d0i * 3 + 1]), __ldg(&pos[d0i * 3 + 2]));
        pev.w = h2u(1.0f, 0.0f);
        spe[wb + er] = pev;
        int s2 = __shfl_sync(F, s0, xrow);
        const char* gx = (const char*)(x + (size_t)s2 * 16 + xh * 8);
        unsigned sa = sx_u + (unsigned)((wb + xrow) * 20 + xh * 8) * 4;
        CP_ASYNC16(sa, gx);
        CP_ASYNC16(sa + 16, gx + 16);
        CP_COMMIT();
    }

    int t = gw, k = 1, p = 0;
    while (true) {
        int t2;
        if (k < KSTAT) {
            t2 = t + nw;                          // static schedule: gw + k*nw
        } else {
            // warp-uniform tail pull: ONE atomic per warp, broadcast to all lanes
            if (lane == 0) {
                t2 = atomicAdd(&g_tailctr, 1);
                if (t2 >= NT16) t2 = -1;
            }
            t2 = __shfl_sync(F, t2, 0);
        }
        const bool hn = (t2 >= 0);
        int pfs = 0, pfd = 0;
        if (hn) {
            int e2 = t2 * 16 + er;
            if (is64) { pfs = ei[2 * e2]; pfd = ei[2 * NEDGE + 2 * e2]; }
            else      { pfs = ei[e2];     pfd = ei[NEDGE + e2]; }
        }
        __syncwarp();

        // ---- MMA1: h1 = gelu(pe @ [W1;b1;0]) ----
        unsigned pA0, pA1;
        LDSM2(pA0, pA1, pe_addr);

        unsigned h1f[4][4];
        #pragma unroll
        for (int kc = 0; kc < 4; kc++)
            #pragma unroll
            for (int par = 0; par < 2; par++) {
                unsigned b = sW1f[(2 * kc + par) * 32 + lane];
                float d[4] = {0.0f, 0.0f, 0.0f, 0.0f};
                MMA16808(d, pA0, pA1, b);
                h1f[kc][2 * par]     = gelu2_pack(d[0], d[1]);
                h1f[kc][2 * par + 1] = gelu2_pack(d[2], d[3]);
            }

        // ---- stage next tile (phase 1): pos LDGs + x via cp.async ----
        float pp0, pp1, pp2, pp3, pp4, pp5;
        if (hn) {
            sdst[p ^ 1][wb + er] = pfd;
            pp0 = __ldg(&pos[pfs * 3 + 0]); pp1 = __ldg(&pos[pfs * 3 + 1]);
            pp2 = __ldg(&pos[pfs * 3 + 2]);
            pp3 = __ldg(&pos[pfd * 3 + 0]); pp4 = __ldg(&pos[pfd * 3 + 1]);
            pp5 = __ldg(&pos[pfd * 3 + 2]);
            int s2 = __shfl_sync(F, pfs, xrow);
            const char* gx = (const char*)(x + (size_t)s2 * 16 + xh * 8);
            unsigned sa = sx_u + (unsigned)((p ^ 1) * 2560 + (wb + xrow) * 20 + xh * 8) * 4;
            CP_ASYNC16(sa, gx);
            CP_ASYNC16(sa + 16, gx + 16);
            CP_COMMIT();
        }

        // ---- MMA2: h2 = gelu(h1 @ Wh + bh), split accumulator chains ----
        unsigned h2f[4][4];
        #pragma unroll
        for (int kc = 0; kc < 4; kc++)
            #pragma unroll
            for (int par = 0; par < 2; par++) {
                int nt = 2 * kc + par;
                unsigned b0, b1r, b2, b3, b4, b5, b6, b7;
                LDSM4(b0, b1r, b2, b3, wh_a + (unsigned)nt * 1024);
                LDSM4(b4, b5, b6, b7, wh_b + (unsigned)nt * 1024);
                float2 bh2 = *(const float2*)&sbh[nt * 8 + 2 * tig];
                float d[4]  = {bh2.x, bh2.y, bh2.x, bh2.y};
                float d2[4] = {0.0f, 0.0f, 0.0f, 0.0f};
                MMA16816(d,  h1f[0][0], h1f[0][1], h1f[0][2], h1f[0][3], b0, b1r);
                MMA16816(d2, h1f[1][0], h1f[1][1], h1f[1][2], h1f[1][3], b2, b3);
                MMA16816(d,  h1f[2][0], h1f[2][1], h1f[2][2], h1f[2][3], b4, b5);
                MMA16816(d2, h1f[3][0], h1f[3][1], h1f[3][2], h1f[3][3], b6, b7);
                h2f[kc][2 * par]     = gelu2_pack(d[0] + d2[0], d[1] + d2[1]);
                h2f[kc][2 * par + 1] = gelu2_pack(d[2] + d2[2], d[3] + d2[3]);
            }

        // ---- stage next tile (phase 2): pack + store pe ----
        if (hn) {
            uint4 pev;
            pev.x = h2u(pp0, pp1); pev.y = h2u(pp2, pp3);
            pev.z = h2u(pp4, pp5); pev.w = h2u(1.0f, 0.0f);
            spe[wb + er] = pev;    // safe: this tile's pe LDSM already done
        }

        // ---- wait for this tile's x (issued last iteration / prologue) ----
        if (hn) { asm volatile("cp.async.wait_group 1;" ::: "memory"); }
        else    { asm volatile("cp.async.wait_group 0;" ::: "memory"); }
        __syncwarp();

        // ---- MMA3: z = h2 @ Wo + bo; fold x-contraction ----
        const float* sxp = &sx[p][0];
        float msg[8];
        #pragma unroll
        for (int q = 0; q < 8; q++) msg[q] = 0.0f;

        #pragma unroll
        for (int ch = 0; ch < 4; ch++) {
            #pragma unroll
            for (int ntp = 0; ntp < 4; ntp++) {
                unsigned prow0 = (unsigned)(ch * 64 + ntp * 16) * 128;
                unsigned prow1 = prow0 + 1024;
                unsigned b0, b1r, b2, b3, b4, b5, b6, b7;
                unsigned c0, c1r, c2, c3, c4, c5, c6, c7;
                LDSM4(b0, b1r, b2, b3, wo_a + prow0);
                LDSM4(b4, b5, b6, b7, wo_b + prow0);
                LDSM4(c0, c1r, c2, c3, wo_a + prow1);
                LDSM4(c4, c5, c6, c7, wo_b + prow1);
                int i = 4 * ch + ntp;
                int cbase = ch * 64 + ntp * 16 + 2 * tig;
                float2 bz0 = *(const float2*)&sbo[cbase];
                float2 bz1 = *(const float2*)&sbo[cbase + 8];
                float xa = sxp[(wb + g) * 20 + i];
                float xb = sxp[(wb + g + 8) * 20 + i];
                float d0[4] = {bz0.x, bz0.y, bz0.x, bz0.y};
                float d1[4] = {bz1.x, bz1.y, bz1.x, bz1.y};
                MMA16816(d0, h2f[0][0], h2f[0][1], h2f[0][2], h2f[0][3], b0, b1r);
                MMA16816(d1, h2f[0][0], h2f[0][1], h2f[0][2], h2f[0][3], c0, c1r);
                MMA16816(d0, h2f[1][0], h2f[1][1], h2f[1][2], h2f[1][3], b2, b3);
                MMA16816(d1, h2f[1][0], h2f[1][1], h2f[1][2], h2f[1][3], c2, c3);
                MMA16816(d0, h2f[2][0], h2f[2][1], h2f[2][2], h2f[2][3], b4, b5);
                MMA16816(d1, h2f[2][0], h2f[2][1], h2f[2][2], h2f[2][3], c4, c5);
                MMA16816(d0, h2f[3][0], h2f[3][1], h2f[3][2], h2f[3][3], b6, b7);
                MMA16816(d1, h2f[3][0], h2f[3][1], h2f[3][2], h2f[3][3], c6, c7);
                msg[0] += d0[0] * xa;  msg[1] += d0[1] * xa;
                msg[4] += d0[2] * xb;  msg[5] += d0[3] * xb;
                msg[2] += d1[0] * xa;  msg[3] += d1[1] * xa;
                msg[6] += d1[2] * xb;  msg[7] += d1[3] * xb;
            }
        }

        // ---- scatter: rows g and g+8, 4 cols each ----
        int dA = sdst[p][wb + g];
        int dB = sdst[p][wb + g + 8];
        #pragma unroll
        for (int q = 0; q < 4; q++) {
            int o = (q >> 1) * 8 + 2 * tig + (q & 1);
            atomicAdd(out + (size_t)dA * 16 + o, msg[q]);
            atomicAdd(out + (size_t)dB * 16 + o, msg[4 + q]);
        }

        if (!hn) break;
        t = t2; k++; p ^= 1;
    }
}

extern "C" void kernel_launch(void* const* d_in, const int* in_sizes, int n_in,
                              void* d_out, int out_size) {
    const float* x   = (const float*)d_in[0];
    const float* pos = (const float*)d_in[1];
    const int*   ei  = (const int*)d_in[2];
    const float* W1  = (const float*)d_in[3];
    const float* b1  = (const float*)d_in[4];
    const float* Wh  = (const float*)d_in[5];
    const float* bh  = (const float*)d_in[6];
    const float* Wo  = (const float*)d_in[7];
    const float* bo  = (const float*)d_in[8];
    float* out = (float*)d_out;

    cudaFuncSetAttribute(edge_kernel, cudaFuncAttributeMaxDynamicSharedMemorySize, 41984);

    init_kernel<<<(NPTS * 16 + 255) / 256, 256>>>(ei, out);
    edge_kernel<<<GRID, 256, 41984>>>(x, pos, ei, W1, b1, bh, Wh, Wo, bo, out);
}

// round 16
// speedup vs baseline: 12.4005x; 1.0029x over previous
#include <cuda_runtime.h>
#include <cuda_fp16.h>

#define NPTS   50000
#define NEDGE  800000
#define NT16   50000      // 16 edges per warp-tile
#define GRID   444
#define NWTOT  (GRID * 8)         // 3552 warps
#define KSTAT  14                 // static tiles per warp
#define TAIL0  (NWTOT * KSTAT)    // 49728

__device__ int g_is64;
__device__ int g_tailctr;

#define SWZ(b) ((b) ^ (((b) >> 3) & 0x70))

__device__ __forceinline__ unsigned smem_u32(const void* p) {
    unsigned a;
    asm("{ .reg .u64 t; cvta.to.shared.u64 t, %1; cvt.u32.u64 %0, t; }" : "=r"(a) : "l"(p));
    return a;
}

#define LDSM2(r0, r1, addr) \
    asm volatile("ldmatrix.sync.aligned.m8n8.x2.shared.b16 {%0,%1}, [%2];" \
        : "=r"(r0), "=r"(r1) : "r"(addr))

#define LDSM4(r0, r1, r2, r3, addr) \
    asm volatile("ldmatrix.sync.aligned.m8n8.x4.shared.b16 {%0,%1,%2,%3}, [%4];" \
        : "=r"(r0), "=r"(r1), "=r"(r2), "=r"(r3) : "r"(addr))

#define MMA16816(d, a0, a1, a2, a3, b0, b1) \
    asm volatile("mma.sync.aligned.m16n8k16.row.col.f32.f16.f16.f32 " \
        "{%0,%1,%2,%3}, {%4,%5,%6,%7}, {%8,%9}, {%0,%1,%2,%3};" \
        : "+f"((d)[0]), "+f"((d)[1]), "+f"((d)[2]), "+f"((d)[3]) \
        : "r"(a0), "r"(a1), "r"(a2), "r"(a3), "r"(b0), "r"(b1))

#define MMA16808(d, a0, a1, b0) \
    asm volatile("mma.sync.aligned.m16n8k8.row.col.f32.f16.f16.f32 " \
        "{%0,%1,%2,%3}, {%4,%5}, {%6}, {%0,%1,%2,%3};" \
        : "+f"((d)[0]), "+f"((d)[1]), "+f"((d)[2]), "+f"((d)[3]) \
        : "r"(a0), "r"(a1), "r"(b0))

#define CP_ASYNC16(smem, gmem) \
    asm volatile("cp.async.ca.shared.global [%0], [%1], 16;" \
        :: "r"(smem), "l"(gmem) : "memory")
#define CP_COMMIT() asm volatile("cp.async.commit_group;" ::: "memory")

// Vector reduction (PTX ISA 8.1+, sm_90+): one instruction, 8B per lane.
#define RED2(ptr, a, b) \
    asm volatile("red.global.add.v2.f32 [%0], {%1, %2};" \
        :: "l"(ptr), "f"(a), "f"(b) : "memory")

__device__ __forceinline__ unsigned h2u(float a, float b) {
    __half2 h = __floats2half2_rn(a, b);
    return *(unsigned*)&h;
}

__device__ __forceinline__ unsigned long long dup2f(float f) {
    unsigned u = __float_as_uint(f);
    return ((unsigned long long)u << 32) | (unsigned long long)u;
}

// Packed-f32x2 branchless gelu pair -> half2 bits.
// erf via A-S 7.1.25 (|eps|<=2.5e-5, << fp16 rounding), sign handled by
// res = 0.5*[(x+|x|) - |x|*(p~*e)] with negated poly (p~ = -P(k)), e = exp(-x^2/2).
__device__ __forceinline__ unsigned gelu2_pack(float a, float b) {
    unsigned long long vx, va, vq, vk, vp, vs;
    float q0, q1;
    asm("mov.b64 %0, {%1, %2};" : "=l"(vx) : "f"(a), "f"(b));
    va = vx & 0x7FFFFFFF7FFFFFFFULL;                                   // |x|
    asm("fma.rn.f32x2 %0, %1, %2, %3;" : "=l"(vq)
        : "l"(va), "l"(dup2f(0.33268194f)), "l"(dup2f(1.0f)));         // 1 + 0.47047*|x|/sqrt2
    asm("mov.b64 {%0, %1}, %2;" : "=f"(q0), "=f"(q1) : "l"(vq));
    asm("rcp.approx.f32 %0, %1;" : "=f"(q0) : "f"(q0));
    asm("rcp.approx.f32 %0, %1;" : "=f"(q1) : "f"(q1));
    asm("mov.b64 %0, {%1, %2};" : "=l"(vk) : "f"(q0), "f"(q1));        // k
    asm("fma.rn.f32x2 %0, %1, %2, %3;" : "=l"(vp)
        : "l"(vk), "l"(dup2f(-0.7478556f)), "l"(dup2f(0.0958798f)));
    asm("fma.rn.f32x2 %0, %1, %2, %3;" : "=l"(vp)
        : "l"(vp), "l"(vk), "l"(dup2f(-0.3480242f)));
    asm("mul.rn.f32x2 %0, %1, %2;" : "=l"(vp) : "l"(vp), "l"(vk));     // -P(k)
    asm("mul.rn.f32x2 %0, %1, %2;" : "=l"(vq) : "l"(vx), "l"(vx));     // x^2
    asm("mul.rn.f32x2 %0, %1, %2;" : "=l"(vq)
        : "l"(vq), "l"(dup2f(-0.72134752f)));                          // -x^2*log2e/2
    asm("mov.b64 {%0, %1}, %2;" : "=f"(q0), "=f"(q1) : "l"(vq));
    asm("ex2.approx.f32 %0, %1;" : "=f"(q0) : "f"(q0));
    asm("ex2.approx.f32 %0, %1;" : "=f"(q1) : "f"(q1));
    asm("mov.b64 %0, {%1, %2};" : "=l"(vq) : "f"(q0), "f"(q1));        // exp(-x^2/2)
    asm("mul.rn.f32x2 %0, %1, %2;" : "=l"(vp) : "l"(vp), "l"(vq));     // -P*e
    asm("add.rn.f32x2 %0, %1, %2;" : "=l"(vs) : "l"(vx), "l"(va));     // x+|x|
    asm("fma.rn.f32x2 %0, %1, %2, %3;" : "=l"(vs) : "l"(va), "l"(vp), "l"(vs));
    asm("mul.rn.f32x2 %0, %1, %2;" : "=l"(vs) : "l"(vs), "l"(dup2f(0.5f)));
    asm("mov.b64 {%0, %1}, %2;" : "=f"(q0), "=f"(q1) : "l"(vs));
    unsigned r;
    asm("cvt.rn.f16x2.f32 %0, %1, %2;" : "=r"(r) : "f"(q1), "f"(q0));  // {lo=g(a), hi=g(b)}
    return r;
}

// -------- init: dtype detect + zero out + tail counter reset --------
__global__ __launch_bounds__(256) void init_kernel(
    const int* __restrict__ ei32, float* __restrict__ out)
{
    int t = blockIdx.x * blockDim.x + threadIdx.x;
    if (blockIdx.x == 0 && threadIdx.x < 32) {
        int lane = threadIdx.x;
        int nz = (ei32[2 * lane + 1] != 0) || (ei32[2 * (lane + 32) + 1] != 0);
        unsigned any = __ballot_sync(0xffffffffu, nz);
        if (lane == 0) g_is64 = (any == 0u);
    }
    if (blockIdx.x == 0 && threadIdx.x == 32) g_tailctr = TAIL0;
    if (t < NPTS * 16) out[t] = 0.0f;
}

// -------- edge kernel: m16 warp-tiles, 3 CTAs/SM, cp.async prefetch, tail pool ----
__global__ __launch_bounds__(256, 3) void edge_kernel(
    const float* __restrict__ x, const float* __restrict__ pos,
    const int* __restrict__ ei,
    const float* __restrict__ W1, const float* __restrict__ b1,
    const float* __restrict__ bh, const float* __restrict__ Wh,
    const float* __restrict__ Wo, const float* __restrict__ bo,
    float* __restrict__ out)
{
    extern __shared__ char dyn[];
    __shared__ float sbh[64];
    __shared__ float sbo[256];
    __shared__ unsigned sW1f[8 * 32];
    __shared__ float sx[2][128 * 20];      // fp32 x, stride 20 (conflict-free, 16B-aligned)
    __shared__ int   sdst[2][128];
    __shared__ __align__(16) uint4 spe[128];

    unsigned dbase = smem_u32(dyn);
    unsigned abase = (dbase + 1023u) & ~1023u;
    char* sp = dyn + (abase - dbase);
    const unsigned WH_OFF = 0, WO_OFF = 8192;
    unsigned WHs = abase + WH_OFF, WOs = abase + WO_OFF;

    int tid = threadIdx.x, lane = tid & 31, wid = tid >> 5;
    const unsigned F = 0xffffffffu;

    if (tid < 64) sbh[tid] = bh[tid];
    if (tid < 256) sbo[tid] = bo[tid];
    if (tid < 32) {      // W1 B-frags (k8n8), bias folded as row 6 (pe[6]=1), row 7 = 0
        int lg = tid >> 2, ltig = tid & 3;
        #pragma unroll
        for (int nt = 0; nt < 8; nt++) {
            int c = nt * 8 + lg;
            sW1f[nt * 32 + tid] = (ltig == 3)
                ? h2u(__ldg(&b1[c]), 0.0f)
                : h2u(__ldg(&W1[(2 * ltig) * 64 + c]), __ldg(&W1[(2 * ltig + 1) * 64 + c]));
        }
    }
    // WhT[c][j] = Wh[j*64+c]  fp16 K-major rows of 128B, SW128
    for (int t = tid; t < 4096; t += 256) {
        int j = t >> 6, c = t & 63;
        *(__half*)(sp + WH_OFF + SWZ(c * 128 + j * 2)) = __float2half_rn(Wh[t]);
    }
    // WoT[p][j] = Wo[j*256+p]
    for (int t = tid; t < 16384; t += 256) {
        int j = t >> 8, p = t & 255;
        *(__half*)(sp + WO_OFF + SWZ(p * 128 + j * 2)) = __float2half_rn(Wo[t]);
    }
    __syncthreads();

    const int is64 = g_is64;
    const int g = lane >> 2, tig = lane & 3;
    const int wb = wid * 16;
    const int er = lane & 15;               // edge slot within tile
    const int xrow = lane >> 1, xh = lane & 1;   // x staging: 2 lanes per row

    // hoisted swizzled B-address bases (1024-multiple row offsets add linearly)
    unsigned wh_a = WHs + SWZ((unsigned)(lane & 7) * 128 + (lane >> 3) * 16);
    unsigned wh_b = WHs + SWZ((unsigned)(lane & 7) * 128 + (4 + (lane >> 3)) * 16);
    unsigned wo_a = WOs + SWZ((unsigned)(lane & 7) * 128 + (lane >> 3) * 16);
    unsigned wo_b = WOs + SWZ((unsigned)(lane & 7) * 128 + (4 + (lane >> 3)) * 16);
    unsigned pe_addr = smem_u32(spe) + (unsigned)(wb + er) * 16;
    unsigned sx_u = smem_u32(sx);

    int gw = blockIdx.x * 8 + wid;
    int nw = NWTOT;

    // ---- prologue: stage tile gw into parity 0 ----
    {
        int e0 = gw * 16 + er;
        int s0, d0i;
        if (is64) { s0 = ei[2 * e0]; d0i = ei[2 * NEDGE + 2 * e0]; }
        else      { s0 = ei[e0];     d0i = ei[NEDGE + e0]; }
        sdst[0][wb + er] = d0i;
        uint4 pev;
        pev.x = h2u(__ldg(&pos[s0 * 3 + 0]), __ldg(&pos[s0 * 3 + 1]));
        pev.y = h2u(__ldg(&pos[s0 * 3 + 2]), __ldg(&pos[d0i * 3 + 0]));
        pev.z = h2u(__ldg(&pos[d0i * 3 + 1]), __ldg(&pos[d0i * 3 + 2]));
        pev.w = h2u(1.0f, 0.0f);
        spe[wb + er] = pev;
        int s2 = __shfl_sync(F, s0, xrow);
        const char* gx = (const char*)(x + (size_t)s2 * 16 + xh * 8);
        unsigned sa = sx_u + (unsigned)((wb + xrow) * 20 + xh * 8) * 4;
        CP_ASYNC16(sa, gx);
        CP_ASYNC16(sa + 16, gx + 16);
        CP_COMMIT();
    }

    int t = gw, k = 1, p = 0;
    while (true) {
        int t2;
        if (k < KSTAT) {
            t2 = t + nw;                          // static schedule: gw + k*nw
        } else {
            // warp-uniform tail pull: ONE atomic per warp, broadcast to all lanes
            if (lane == 0) {
                t2 = atomicAdd(&g_tailctr, 1);
                if (t2 >= NT16) t2 = -1;
            }
            t2 = __shfl_sync(F, t2, 0);
        }
        const bool hn = (t2 >= 0);
        int pfs = 0, pfd = 0;
        if (hn) {
            int e2 = t2 * 16 + er;
            if (is64) { pfs = ei[2 * e2]; pfd = ei[2 * NEDGE + 2 * e2]; }
            else      { pfs = ei[e2];     pfd = ei[NEDGE + e2]; }
        }
        __syncwarp();

        // ---- MMA1: h1 = gelu(pe @ [W1;b1;0]) ----
        unsigned pA0, pA1;
        LDSM2(pA0, pA1, pe_addr);

        unsigned h1f[4][4];
        #pragma unroll
        for (int kc = 0; kc < 4; kc++)
            #pragma unroll
            for (int par = 0; par < 2; par++) {
                unsigned b = sW1f[(2 * kc + par) * 32 + lane];
                float d[4] = {0.0f, 0.0f, 0.0f, 0.0f};
                MMA16808(d, pA0, pA1, b);
                h1f[kc][2 * par]     = gelu2_pack(d[0], d[1]);
                h1f[kc][2 * par + 1] = gelu2_pack(d[2], d[3]);
            }

        // ---- stage next tile (phase 1): pos LDGs + x via cp.async ----
        float pp0, pp1, pp2, pp3, pp4, pp5;
        if (hn) {
            sdst[p ^ 1][wb + er] = pfd;
            pp0 = __ldg(&pos[pfs * 3 + 0]); pp1 = __ldg(&pos[pfs * 3 + 1]);
            pp2 = __ldg(&pos[pfs * 3 + 2]);
            pp3 = __ldg(&pos[pfd * 3 + 0]); pp4 = __ldg(&pos[pfd * 3 + 1]);
            pp5 = __ldg(&pos[pfd * 3 + 2]);
            int s2 = __shfl_sync(F, pfs, xrow);
            const char* gx = (const char*)(x + (size_t)s2 * 16 + xh * 8);
            unsigned sa = sx_u + (unsigned)((p ^ 1) * 2560 + (wb + xrow) * 20 + xh * 8) * 4;
            CP_ASYNC16(sa, gx);
            CP_ASYNC16(sa + 16, gx + 16);
            CP_COMMIT();
        }

        // ---- MMA2: h2 = gelu(h1 @ Wh + bh), split accumulator chains ----
        unsigned h2f[4][4];
        #pragma unroll
        for (int kc = 0; kc < 4; kc++)
            #pragma unroll
            for (int par = 0; par < 2; par++) {
                int nt = 2 * kc + par;
                unsigned b0, b1r, b2, b3, b4, b5, b6, b7;
                LDSM4(b0, b1r, b2, b3, wh_a + (unsigned)nt * 1024);
                LDSM4(b4, b5, b6, b7, wh_b + (unsigned)nt * 1024);
                float2 bh2 = *(const float2*)&sbh[nt * 8 + 2 * tig];
                float d[4]  = {bh2.x, bh2.y, bh2.x, bh2.y};
                float d2[4] = {0.0f, 0.0f, 0.0f, 0.0f};
                MMA16816(d,  h1f[0][0], h1f[0][1], h1f[0][2], h1f[0][3], b0, b1r);
                MMA16816(d2, h1f[1][0], h1f[1][1], h1f[1][2], h1f[1][3], b2, b3);
                MMA16816(d,  h1f[2][0], h1f[2][1], h1f[2][2], h1f[2][3], b4, b5);
                MMA16816(d2, h1f[3][0], h1f[3][1], h1f[3][2], h1f[3][3], b6, b7);
                h2f[kc][2 * par]     = gelu2_pack(d[0] + d2[0], d[1] + d2[1]);
                h2f[kc][2 * par + 1] = gelu2_pack(d[2] + d2[2], d[3] + d2[3]);
            }

        // ---- stage next tile (phase 2): pack + store pe ----
        if (hn) {
            uint4 pev;
            pev.x = h2u(pp0, pp1); pev.y = h2u(pp2, pp3);
            pev.z = h2u(pp4, pp5); pev.w = h2u(1.0f, 0.0f);
            spe[wb + er] = pev;    // safe: this tile's pe LDSM already done
        }

        // ---- wait for this tile's x (issued last iteration / prologue) ----
        if (hn) { asm volatile("cp.async.wait_group 1;" ::: "memory"); }
        else    { asm volatile("cp.async.wait_group 0;" ::: "memory"); }
        __syncwarp();

        // ---- MMA3: z = h2 @ Wo + bo; fold x-contraction; float4 x loads per ch ----
        const float* sxp = &sx[p][0];
        float msg[8];
        #pragma unroll
        for (int q = 0; q < 8; q++) msg[q] = 0.0f;

        #pragma unroll
        for (int ch = 0; ch < 4; ch++) {
            float4 xva = *(const float4*)&sxp[(wb + g) * 20 + 4 * ch];       // x[row g, 4ch..4ch+3]
            float4 xvb = *(const float4*)&sxp[(wb + g + 8) * 20 + 4 * ch];   // x[row g+8, ...]
            const float xar[4] = {xva.x, xva.y, xva.z, xva.w};
            const float xbr[4] = {xvb.x, xvb.y, xvb.z, xvb.w};
            #pragma unroll
            for (int ntp = 0; ntp < 4; ntp++) {
                unsigned prow0 = (unsigned)(ch * 64 + ntp * 16) * 128;
                unsigned prow1 = prow0 + 1024;
                unsigned b0, b1r, b2, b3, b4, b5, b6, b7;
                unsigned c0, c1r, c2, c3, c4, c5, c6, c7;
                LDSM4(b0, b1r, b2, b3, wo_a + prow0);
                LDSM4(b4, b5, b6, b7, wo_b + prow0);
                LDSM4(c0, c1r, c2, c3, wo_a + prow1);
                LDSM4(c4, c5, c6, c7, wo_b + prow1);
                int cbase = ch * 64 + ntp * 16 + 2 * tig;
                float2 bz0 = *(const float2*)&sbo[cbase];
                float2 bz1 = *(const float2*)&sbo[cbase + 8];
                float xa = xar[ntp];
                float xb = xbr[ntp];
                float d0[4] = {bz0.x, bz0.y, bz0.x, bz0.y};
                float d1[4] = {bz1.x, bz1.y, bz1.x, bz1.y};
                MMA16816(d0, h2f[0][0], h2f[0][1], h2f[0][2], h2f[0][3], b0, b1r);
                MMA16816(d1, h2f[0][0], h2f[0][1], h2f[0][2], h2f[0][3], c0, c1r);
                MMA16816(d0, h2f[1][0], h2f[1][1], h2f[1][2], h2f[1][3], b2, b3);
                MMA16816(d1, h2f[1][0], h2f[1][1], h2f[1][2], h2f[1][3], c2, c3);
                MMA16816(d0, h2f[2][0], h2f[2][1], h2f[2][2], h2f[2][3], b4, b5);
                MMA16816(d1, h2f[2][0], h2f[2][1], h2f[2][2], h2f[2][3], c4, c5);
                MMA16816(d0, h2f[3][0], h2f[3][1], h2f[3][2], h2f[3][3], b6, b7);
                MMA16816(d1, h2f[3][0], h2f[3][1], h2f[3][2], h2f[3][3], c6, c7);
                msg[0] += d0[0] * xa;  msg[1] += d0[1] * xa;
                msg[4] += d0[2] * xb;  msg[5] += d0[3] * xb;
                msg[2] += d1[0] * xa;  msg[3] += d1[1] * xa;
                msg[6] += d1[2] * xb;  msg[7] += d1[3] * xb;
            }
        }

        // ---- scatter: vector red (o pairs adjacent, 8B aligned) ----
        int dA = sdst[p][wb + g];
        int dB = sdst[p][wb + g + 8];
        float* pA = out + (size_t)dA * 16 + 2 * tig;
        float* pB = out + (size_t)dB * 16 + 2 * tig;
        RED2(pA,     msg[0], msg[1]);
        RED2(pA + 8, msg[2], msg[3]);
        RED2(pB,     msg[4], msg[5]);
        RED2(pB + 8, msg[6], msg[7]);

        if (!hn) break;
        t = t2; k++; p ^= 1;
    }
}

extern "C" void kernel_launch(void* const* d_in, const int* in_sizes, int n_in,
                              void* d_out, int out_size) {
    const float* x   = (const float*)d_in[0];
    const float* pos = (const float*)d_in[1];
    const int*   ei  = (const int*)d_in[2];
    const float* W1  = (const float*)d_in[3];
    const float* b1  = (const float*)d_in[4];
    const float* Wh  = (const float*)d_in[5];
    const float* bh  = (const float*)d_in[6];
    const float* Wo  = (const float*)d_in[7];
    const float* bo  = (const float*)d_in[8];
    float* out = (float*)d_out;

    cudaFuncSetAttribute(edge_kernel, cudaFuncAttributeMaxDynamicSharedMemorySize, 41984);

    init_kernel<<<(NPTS * 16 + 255) / 256, 256>>>(ei, out);
    edge_kernel<<<GRID, 256, 41984>>>(x, pos, ei, W1, b1, bh, Wh, Wo, bo, out);
}